// round 11
// baseline (speedup 1.0000x reference)
#include <cuda_runtime.h>
#include <cuda_bf16.h>
#include <cstdint>

using bf16 = __nv_bfloat16;

// CrossAttention B=4, N=M=1024, DIM=1024, H=16, d=vd=64.
// All GEMMs: warp-level HMMA (mma.sync bf16, sm_80-baseline PTX) with bf16x3
// split precision (hi*hi + hi*lo + lo*hi), fp32 accumulators.
// R11: K-chunk 32 + SW64 smem, 3-4 stage cp.async pipeline, 1 sync/iter.

// ---------------------------------------------------------------- scratch
__device__ __align__(16) bf16 g_xhi[4194304], g_xlo[4194304];     // x split
__device__ __align__(16) bf16 g_chi[4194304], g_clo[4194304];     // ctx split
__device__ __align__(16) bf16 g_wqhi[1048576], g_wqlo[1048576];   // Wq^T  [out][in]
__device__ __align__(16) bf16 g_wkhi[2097152], g_wklo[2097152];   // Wkv^T [out][in]
__device__ __align__(16) bf16 g_qhi[4194304], g_qlo[4194304];     // q*0.125 [b*N+i][h*64+d]
__device__ __align__(16) bf16 g_khi[4194304], g_klo[4194304];     // k       [b*M+j][h*64+d]
__device__ __align__(16) bf16 g_vthi[4194304], g_vtlo[4194304];   // v^T [b][h*64+vd][j]
__device__ float g_w[67108864];                                   // scores fp32 [b,h,i,j]
__device__ __align__(16) bf16 g_whi[67108864], g_wlo[67108864];   // post-softtalk w split

// ---------------------------------------------------------------- helpers
__device__ __forceinline__ uint32_t smem_u32(const void* p) {
    uint32_t a;
    asm("{ .reg .u64 t; cvta.to.shared.u64 t, %1; cvt.u32.u64 %0, t; }" : "=r"(a) : "l"(p));
    return a;
}
__device__ __forceinline__ void split2(float v, unsigned short& h, unsigned short& l) {
    bf16 hb = __float2bfloat16(v);
    h = __bfloat16_as_ushort(hb);
    l = __bfloat16_as_ushort(__float2bfloat16(v - __bfloat162float(hb)));
}
#define SWZ64(x) ((x) ^ (((x) >> 3) & 0x30))

__device__ __forceinline__ void cpa16(uint32_t dst, const void* src) {
    asm volatile("cp.async.cg.shared.global [%0], [%1], 16;" :: "r"(dst), "l"(src));
}
__device__ __forceinline__ void ldsm4(uint32_t r[4], uint32_t addr) {
    asm volatile("ldmatrix.sync.aligned.m8n8.x4.shared.b16 {%0,%1,%2,%3}, [%4];"
                 : "=r"(r[0]), "=r"(r[1]), "=r"(r[2]), "=r"(r[3]) : "r"(addr));
}
__device__ __forceinline__ void mma_bf16(float c[4], const uint32_t a[4], const uint32_t b[2]) {
    asm volatile(
        "mma.sync.aligned.m16n8k16.row.col.f32.bf16.bf16.f32 "
        "{%0,%1,%2,%3}, {%4,%5,%6,%7}, {%8,%9}, {%0,%1,%2,%3};"
        : "+f"(c[0]), "+f"(c[1]), "+f"(c[2]), "+f"(c[3])
        : "r"(a[0]), "r"(a[1]), "r"(a[2]), "r"(a[3]), "r"(b[0]), "r"(b[1]));
}

// ---------------------------------------------------------------- prep kernels
__global__ __launch_bounds__(256) void split_kernel(const float* __restrict__ s,
                                                    bf16* __restrict__ hi, bf16* __restrict__ lo) {
    size_t i = (size_t)blockIdx.x * 256 + threadIdx.x;
    float4 v = ((const float4*)s)[i];
    unsigned short hh[4], ll[4];
    split2(v.x, hh[0], ll[0]); split2(v.y, hh[1], ll[1]);
    split2(v.z, hh[2], ll[2]); split2(v.w, hh[3], ll[3]);
    ((uint2*)hi)[i] = *(uint2*)hh;
    ((uint2*)lo)[i] = *(uint2*)ll;
}

__global__ void tsplit_kernel(const float* __restrict__ s, bf16* __restrict__ hi,
                              bf16* __restrict__ lo, int R, int C) {
    __shared__ float t[32][33];
    const int c0 = blockIdx.x * 32, r0 = blockIdx.y * 32;
    const int tx = threadIdx.x, ty = threadIdx.y;
#pragma unroll
    for (int k = 0; k < 4; ++k)
        t[ty + 8 * k][tx] = s[(size_t)(r0 + ty + 8 * k) * C + c0 + tx];
    __syncthreads();
#pragma unroll
    for (int k = 0; k < 4; ++k) {
        unsigned short h, l;
        split2(t[tx][ty + 8 * k], h, l);
        const size_t o = (size_t)(c0 + ty + 8 * k) * R + r0 + tx;
        hi[o] = __ushort_as_bfloat16(h);
        lo[o] = __ushort_as_bfloat16(l);
    }
}

// ---------------------------------------------------------------- HMMA GEMM
// C[128 x BN] per CTA = sum_k A[m][k]*B[n][k]  (A,B K-major bf16 hi/lo planes).
// K-chunk 32 (64B smem rows, SW64), NSTAGE-deep cp.async pipeline, 1 sync/iter.
// Per-z offsets: (z>>4)*S1 + (z&15)*S2 elements.
template<int BN, int KDIM, int NSTAGE, bool SPLIT_OUT>
__global__ __launch_bounds__(256)
void hmma_gemm(const bf16* __restrict__ Ahi, const bf16* __restrict__ Alo,
               int64_t aS1, int64_t aS2, int64_t lda,
               const bf16* __restrict__ Bhi, const bf16* __restrict__ Blo,
               int64_t bS1, int64_t bS2, int64_t ldb,
               float* __restrict__ Cf, bf16* __restrict__ Chi, bf16* __restrict__ Clo,
               int64_t cS1, int64_t cS2, int64_t ldc, float scale)
{
    constexpr int NC    = KDIM / 32;            // 32-wide K chunks
    constexpr int AST   = 128 * 64;             // bytes per A plane per stage
    constexpr int BST   = BN * 64;
    constexpr int STG   = 2 * AST + 2 * BST;
    constexpr int NWN   = BN / 4;               // warp n-extent (32 or 16)
    constexpr int NFRAG = BN / 32;              // n-frags per warp (4 or 2)

    extern __shared__ char smem[];
    const uint32_t sb = smem_u32(smem);
    const int tid = threadIdx.x, lane = tid & 31, wid = tid >> 5;
    const int wm = wid >> 2, wn = wid & 3;

    const int z = blockIdx.z;
    const int64_t aB = (int64_t)(z >> 4) * aS1 + (int64_t)(z & 15) * aS2
                     + (int64_t)blockIdx.y * 128 * lda;
    const int64_t bB = (int64_t)(z >> 4) * bS1 + (int64_t)(z & 15) * bS2
                     + (int64_t)blockIdx.x * BN * ldb;
    const int64_t cB = (int64_t)(z >> 4) * cS1 + (int64_t)(z & 15) * cS2
                     + (int64_t)blockIdx.y * 128 * ldc + (int64_t)blockIdx.x * BN;

    float cf[4][NFRAG][4];
#pragma unroll
    for (int mf = 0; mf < 4; ++mf)
#pragma unroll
        for (int nf = 0; nf < NFRAG; ++nf)
#pragma unroll
            for (int q = 0; q < 4; ++q) cf[mf][nf][q] = 0.f;

    auto issue = [&](int c) {
        const uint32_t so = sb + (c % NSTAGE) * STG;
        const bf16* ah = Ahi + aB + c * 32;
        const bf16* al = Alo + aB + c * 32;
#pragma unroll
        for (int i = tid; i < 512; i += 256) {              // A: 128 rows x 4 segs(16B)
            const int r = i >> 2, g = i & 3;
            const uint32_t sw = SWZ64(r * 64 + g * 16);
            const int64_t go = (int64_t)r * lda + g * 8;
            cpa16(so + sw, ah + go);
            cpa16(so + AST + sw, al + go);
        }
        const bf16* bh = Bhi + bB + c * 32;
        const bf16* bl = Blo + bB + c * 32;
#pragma unroll
        for (int i = tid; i < BN * 4; i += 256) {           // B: BN rows x 4 segs
            const int r = i >> 2, g = i & 3;
            const uint32_t sw = SWZ64(r * 64 + g * 16);
            const int64_t go = (int64_t)r * ldb + g * 8;
            cpa16(so + 2 * AST + sw, bh + go);
            cpa16(so + 2 * AST + BST + sw, bl + go);
        }
        asm volatile("cp.async.commit_group;" ::: "memory");
    };

    const int l8 = lane & 7, sub = lane >> 3;
    const int arow = wm * 64 + l8 + (sub & 1) * 8;          // + mf*16
    const int asegsel = sub >> 1;
    const int brow = wn * NWN + l8 + (sub >> 1) * 8;        // + nb*8
    const int bsegsel = sub & 1;

    auto compute = [&](int c) {
        const uint32_t sA  = sb + (c % NSTAGE) * STG;
        const uint32_t sBh = sA + 2 * AST;
#pragma unroll
        for (int kk = 0; kk < 2; ++kk) {                    // 2 x k16 per chunk
            uint32_t af[2][4][4];
#pragma unroll
            for (int mf = 0; mf < 4; ++mf) {
                const uint32_t ad = sA + SWZ64((arow + mf * 16) * 64 + (kk * 2 + asegsel) * 16);
                ldsm4(af[0][mf], ad);
                ldsm4(af[1][mf], ad + AST);
            }
            uint32_t bfr[2][NFRAG][2];
#pragma unroll
            for (int nb = 0; nb < NFRAG; nb += 2) {
                const uint32_t bd = SWZ64((brow + nb * 8) * 64 + (kk * 2 + bsegsel) * 16);
                uint32_t t[4];
                ldsm4(t, sBh + bd);
                bfr[0][nb][0] = t[0]; bfr[0][nb][1] = t[1];
                bfr[0][nb + 1][0] = t[2]; bfr[0][nb + 1][1] = t[3];
                ldsm4(t, sBh + BST + bd);
                bfr[1][nb][0] = t[0]; bfr[1][nb][1] = t[1];
                bfr[1][nb + 1][0] = t[2]; bfr[1][nb + 1][1] = t[3];
            }
#pragma unroll
            for (int mf = 0; mf < 4; ++mf)
#pragma unroll
                for (int nf = 0; nf < NFRAG; ++nf) {
                    mma_bf16(cf[mf][nf], af[0][mf], bfr[0][nf]);   // hi*hi
                    mma_bf16(cf[mf][nf], af[0][mf], bfr[1][nf]);   // hi*lo
                    mma_bf16(cf[mf][nf], af[1][mf], bfr[0][nf]);   // lo*hi
                }
        }
    };

    // prologue: NSTAGE-1 chunks in flight
#pragma unroll
    for (int c = 0; c < NSTAGE - 1 && c < NC; ++c) issue(c);

    // steady state: wait -> sync -> issue(or empty commit, keeps group count) -> compute
    for (int c = 0; c < NC; ++c) {
        asm volatile("cp.async.wait_group %0;" :: "n"(NSTAGE - 2) : "memory");
        __syncthreads();
        if (c + NSTAGE - 1 < NC) issue(c + NSTAGE - 1);
        else asm volatile("cp.async.commit_group;" ::: "memory");
        compute(c);
    }

    const int crow0 = wm * 64 + lane / 4;
    const int ccol0 = wn * NWN + (lane % 4) * 2;
#pragma unroll
    for (int mf = 0; mf < 4; ++mf)
#pragma unroll
        for (int nf = 0; nf < NFRAG; ++nf) {
            const int64_t o0 = cB + (int64_t)(crow0 + mf * 16) * ldc + ccol0 + nf * 8;
            const int64_t o1 = o0 + 8 * ldc;
            if constexpr (SPLIT_OUT) {
                unsigned short h0, l0, h1, l1;
                split2(cf[mf][nf][0] * scale, h0, l0);
                split2(cf[mf][nf][1] * scale, h1, l1);
                *(uint32_t*)&Chi[o0] = (uint32_t)h0 | ((uint32_t)h1 << 16);
                *(uint32_t*)&Clo[o0] = (uint32_t)l0 | ((uint32_t)l1 << 16);
                split2(cf[mf][nf][2] * scale, h0, l0);
                split2(cf[mf][nf][3] * scale, h1, l1);
                *(uint32_t*)&Chi[o1] = (uint32_t)h0 | ((uint32_t)h1 << 16);
                *(uint32_t*)&Clo[o1] = (uint32_t)l0 | ((uint32_t)l1 << 16);
            } else {
                *(float2*)&Cf[o0] = make_float2(cf[mf][nf][0], cf[mf][nf][1]);
                *(float2*)&Cf[o1] = make_float2(cf[mf][nf][2], cf[mf][nf][3]);
            }
        }
}

// ---------------------------------------------------------------- softmax + talking heads + LN
// One block per (b,i): 16 heads x 1024 j. Reads g_w fp32, writes g_whi/g_wlo bf16 split.
__global__ __launch_bounds__(256) void softtalk_kernel(
    const float* __restrict__ Wt, const float* __restrict__ gamma, const float* __restrict__ beta)
{
    extern __shared__ float sm[];        // [0:256) Wt, [256:272) gamma, [288:304) beta, rows @512
    float* rows = sm + 512;              // 16 rows x 1028
    const int tid = threadIdx.x;
    sm[tid] = Wt[tid];
    if (tid < 16) { sm[256 + tid] = gamma[tid]; sm[288 + tid] = beta[tid]; }
    const int b = blockIdx.x >> 10, i = blockIdx.x & 1023;
    const size_t base = ((size_t)b * 16) << 20;
    const size_t irow = (size_t)i * 1024;
#pragma unroll
    for (int h = 0; h < 16; ++h)
        *(float4*)(rows + h * 1028 + tid * 4) =
            *(const float4*)(g_w + base + ((size_t)h << 20) + irow + tid * 4);
    __syncthreads();

    const int wid = tid >> 5, lane = tid & 31;
#pragma unroll
    for (int rr = wid; rr < 16; rr += 8) {
        float* r = rows + rr * 1028;
        float mx = -1e30f;
        for (int j = lane; j < 1024; j += 32) mx = fmaxf(mx, r[j]);
#pragma unroll
        for (int o = 16; o; o >>= 1) mx = fmaxf(mx, __shfl_xor_sync(~0u, mx, o));
        float s = 0.f;
        for (int j = lane; j < 1024; j += 32) { float e = __expf(r[j] - mx); r[j] = e; s += e; }
#pragma unroll
        for (int o = 16; o; o >>= 1) s += __shfl_xor_sync(~0u, s, o);
        const float inv = 1.f / s;
        for (int j = lane; j < 1024; j += 32) r[j] *= inv;
    }
    __syncthreads();

#pragma unroll
    for (int jj = 0; jj < 4; ++jj) {
        const int j = tid + jj * 256;
        float o[16];
#pragma unroll
        for (int g = 0; g < 16; ++g) o[g] = 0.f;
#pragma unroll
        for (int h = 0; h < 16; ++h) {
            const float v = rows[h * 1028 + j];
#pragma unroll
            for (int g = 0; g < 16; ++g) o[g] = fmaf(v, sm[h * 16 + g], o[g]);
        }
        float mu = 0.f;
#pragma unroll
        for (int g = 0; g < 16; ++g) mu += o[g];
        mu *= 0.0625f;
        float var = 0.f;
#pragma unroll
        for (int g = 0; g < 16; ++g) { const float dd = o[g] - mu; var = fmaf(dd, dd, var); }
        var *= 0.0625f;
        const float rstd = rsqrtf(var + 1e-5f);
#pragma unroll
        for (int g = 0; g < 16; ++g) {
            const float val = (o[g] - mu) * rstd * sm[256 + g] + sm[288 + g];
            unsigned short h16, l16;
            split2(val, h16, l16);
            const size_t oo = base + ((size_t)g << 20) + irow + j;
            g_whi[oo] = __ushort_as_bfloat16(h16);
            g_wlo[oo] = __ushort_as_bfloat16(l16);
        }
    }
}

// ---------------------------------------------------------------- launch
extern "C" void kernel_launch(void* const* d_in, const int* in_sizes, int n_in,
                              void* d_out, int out_size) {
    (void)in_sizes; (void)n_in; (void)out_size;
    const float* x   = (const float*)d_in[0];
    const float* ctx = (const float*)d_in[1];
    const float* Wq  = (const float*)d_in[2];
    const float* Wkv = (const float*)d_in[3];
    const float* Wt  = (const float*)d_in[4];
    const float* gm  = (const float*)d_in[5];
    const float* bt  = (const float*)d_in[6];
    float* out = (float*)d_out;

    bf16 *xhi, *xlo, *chi, *clo, *wqh, *wql, *wkh, *wkl;
    bf16 *qh, *ql, *kh, *kl, *vth, *vtl, *whi, *wlo;
    float* gw;
    cudaGetSymbolAddress((void**)&xhi, g_xhi);   cudaGetSymbolAddress((void**)&xlo, g_xlo);
    cudaGetSymbolAddress((void**)&chi, g_chi);   cudaGetSymbolAddress((void**)&clo, g_clo);
    cudaGetSymbolAddress((void**)&wqh, g_wqhi);  cudaGetSymbolAddress((void**)&wql, g_wqlo);
    cudaGetSymbolAddress((void**)&wkh, g_wkhi);  cudaGetSymbolAddress((void**)&wkl, g_wklo);
    cudaGetSymbolAddress((void**)&qh,  g_qhi);   cudaGetSymbolAddress((void**)&ql,  g_qlo);
    cudaGetSymbolAddress((void**)&kh,  g_khi);   cudaGetSymbolAddress((void**)&kl,  g_klo);
    cudaGetSymbolAddress((void**)&vth, g_vthi);  cudaGetSymbolAddress((void**)&vtl, g_vtlo);
    cudaGetSymbolAddress((void**)&whi, g_whi);   cudaGetSymbolAddress((void**)&wlo, g_wlo);
    cudaGetSymbolAddress((void**)&gw,  g_w);

    // stage sizes: BN=128 -> 32KB, BN=64 -> 24KB
    constexpr int SMEM_BIG = 3 * 32768;   // proj/k/vt: 3-stage, 96KB (2 CTAs/SM possible)
    constexpr int SMEM_DOT = 2 * 32768;   // dots: 2-stage, 64KB (3 CTAs/SM)
    constexpr int SMEM_ATT = 4 * 24576;   // attnv: 4-stage, 96KB
    constexpr int SST      = (512 + 16 * 1028) * 4;
    cudaFuncSetAttribute(hmma_gemm<128, 1024, 3, true >, cudaFuncAttributeMaxDynamicSharedMemorySize, SMEM_BIG);
    cudaFuncSetAttribute(hmma_gemm<128,   64, 2, false>, cudaFuncAttributeMaxDynamicSharedMemorySize, SMEM_DOT);
    cudaFuncSetAttribute(hmma_gemm< 64, 1024, 4, false>, cudaFuncAttributeMaxDynamicSharedMemorySize, SMEM_ATT);
    cudaFuncSetAttribute(softtalk_kernel,                cudaFuncAttributeMaxDynamicSharedMemorySize, SST);

    const int64_t M20 = 1 << 20;

    split_kernel<<<4096, 256>>>(x, xhi, xlo);
    split_kernel<<<4096, 256>>>(ctx, chi, clo);
    tsplit_kernel<<<dim3(32, 32), dim3(32, 8)>>>(Wq,  wqh, wql, 1024, 1024);
    tsplit_kernel<<<dim3(64, 32), dim3(32, 8)>>>(Wkv, wkh, wkl, 1024, 2048);

    // q = 0.125 * x @ Wq        [4096 x 1024 x 1024]
    hmma_gemm<128, 1024, 3, true><<<dim3(8, 32, 1), 256, SMEM_BIG>>>(
        xhi, xlo, 0, 0, 1024,  wqh, wql, 0, 0, 1024,
        nullptr, qh, ql, 0, 0, 1024, 0.125f);
    // k = ctx @ Wkv[:, :1024]   [4096 x 1024 x 1024]
    hmma_gemm<128, 1024, 3, true><<<dim3(8, 32, 1), 256, SMEM_BIG>>>(
        chi, clo, 0, 0, 1024,  wkh, wkl, 0, 0, 1024,
        nullptr, kh, kl, 0, 0, 1024, 1.f);
    // vt[b][h*64+vd][j] = Wkv_v^T @ ctx_b^T   (4 batches of 1024 x 1024 x 1024)
    hmma_gemm<128, 1024, 3, true><<<dim3(8, 8, 4), 256, SMEM_BIG>>>(
        wkh + M20, wkl + M20, 0, 0, 1024,  chi, clo, 0, M20, 1024,
        nullptr, vth, vtl, 0, M20, 1024, 1.f);
    // dots: per (b,h) 1024 x 1024 x 64 -> g_w fp32
    hmma_gemm<128, 64, 2, false><<<dim3(8, 8, 64), 256, SMEM_DOT>>>(
        qh, ql, M20, 64, 1024,  kh, kl, M20, 64, 1024,
        gw, nullptr, nullptr, 16 * M20, M20, 1024, 1.f);
    // softmax + talking + LN -> g_whi/g_wlo
    softtalk_kernel<<<4096, 256, SST>>>(Wt, gm, bt);
    // out = w @ v : per (b,h) 1024 x 64 x 1024, scattered into d_out
    hmma_gemm<64, 1024, 4, false><<<dim3(1, 8, 64), 256, SMEM_ATT>>>(
        whi, wlo, 16 * M20, M20, 1024,  vth, vtl, M20, 65536, 1024,
        out, nullptr, nullptr, M20, 64, 1024, 1.f);
}

// round 12
// speedup vs baseline: 1.0018x; 1.0018x over previous
#include <cuda_runtime.h>
#include <cuda_bf16.h>
#include <cstdint>

using bf16 = __nv_bfloat16;

// CrossAttention B=4, N=M=1024, DIM=1024, H=16, d=vd=64.
// HMMA (mma.sync bf16) with bf16x3 split precision, fp32 accumulators.
// R12: R10 base (K-chunk 64, SW128) + single-sync pipelined loop +
//      3-stage prefetch on deep-K GEMMs + merged q/k/vt projection launch.

// ---------------------------------------------------------------- scratch
__device__ __align__(16) bf16 g_xhi[4194304], g_xlo[4194304];     // x split
__device__ __align__(16) bf16 g_chi[4194304], g_clo[4194304];     // ctx split
__device__ __align__(16) bf16 g_wqhi[1048576], g_wqlo[1048576];   // Wq^T  [out][in]
__device__ __align__(16) bf16 g_wkhi[2097152], g_wklo[2097152];   // Wkv^T [out][in]
__device__ __align__(16) bf16 g_qhi[4194304], g_qlo[4194304];     // q*0.125 [b*N+i][h*64+d]
__device__ __align__(16) bf16 g_khi[4194304], g_klo[4194304];     // k       [b*M+j][h*64+d]
__device__ __align__(16) bf16 g_vthi[4194304], g_vtlo[4194304];   // v^T [b][h*64+vd][j]
__device__ float g_w[67108864];                                   // scores fp32 [b,h,i,j]
__device__ __align__(16) bf16 g_whi[67108864], g_wlo[67108864];   // post-softtalk w split

// ---------------------------------------------------------------- helpers
__device__ __forceinline__ uint32_t smem_u32(const void* p) {
    uint32_t a;
    asm("{ .reg .u64 t; cvta.to.shared.u64 t, %1; cvt.u32.u64 %0, t; }" : "=r"(a) : "l"(p));
    return a;
}
__device__ __forceinline__ void split2(float v, unsigned short& h, unsigned short& l) {
    bf16 hb = __float2bfloat16(v);
    h = __bfloat16_as_ushort(hb);
    l = __bfloat16_as_ushort(__float2bfloat16(v - __bfloat162float(hb)));
}
#define SWZ(x) ((x) ^ (((x) >> 3) & 0x70))

__device__ __forceinline__ void cpa16(uint32_t dst, const void* src) {
    asm volatile("cp.async.cg.shared.global [%0], [%1], 16;" :: "r"(dst), "l"(src));
}
__device__ __forceinline__ void ldsm4(uint32_t r[4], uint32_t addr) {
    asm volatile("ldmatrix.sync.aligned.m8n8.x4.shared.b16 {%0,%1,%2,%3}, [%4];"
                 : "=r"(r[0]), "=r"(r[1]), "=r"(r[2]), "=r"(r[3]) : "r"(addr));
}
__device__ __forceinline__ void mma_bf16(float c[4], const uint32_t a[4], const uint32_t b[2]) {
    asm volatile(
        "mma.sync.aligned.m16n8k16.row.col.f32.bf16.bf16.f32 "
        "{%0,%1,%2,%3}, {%4,%5,%6,%7}, {%8,%9}, {%0,%1,%2,%3};"
        : "+f"(c[0]), "+f"(c[1]), "+f"(c[2]), "+f"(c[3])
        : "r"(a[0]), "r"(a[1]), "r"(a[2]), "r"(a[3]), "r"(b[0]), "r"(b[1]));
}

// ---------------------------------------------------------------- prep kernels
__global__ __launch_bounds__(256) void split_kernel(const float* __restrict__ s,
                                                    bf16* __restrict__ hi, bf16* __restrict__ lo) {
    size_t i = (size_t)blockIdx.x * 256 + threadIdx.x;
    float4 v = ((const float4*)s)[i];
    unsigned short hh[4], ll[4];
    split2(v.x, hh[0], ll[0]); split2(v.y, hh[1], ll[1]);
    split2(v.z, hh[2], ll[2]); split2(v.w, hh[3], ll[3]);
    ((uint2*)hi)[i] = *(uint2*)hh;
    ((uint2*)lo)[i] = *(uint2*)ll;
}

__global__ void tsplit_kernel(const float* __restrict__ s, bf16* __restrict__ hi,
                              bf16* __restrict__ lo, int R, int C) {
    __shared__ float t[32][33];
    const int c0 = blockIdx.x * 32, r0 = blockIdx.y * 32;
    const int tx = threadIdx.x, ty = threadIdx.y;
#pragma unroll
    for (int k = 0; k < 4; ++k)
        t[ty + 8 * k][tx] = s[(size_t)(r0 + ty + 8 * k) * C + c0 + tx];
    __syncthreads();
#pragma unroll
    for (int k = 0; k < 4; ++k) {
        unsigned short h, l;
        split2(t[tx][ty + 8 * k], h, l);
        const size_t o = (size_t)(c0 + ty + 8 * k) * R + r0 + tx;
        hi[o] = __ushort_as_bfloat16(h);
        lo[o] = __ushort_as_bfloat16(l);
    }
}

// ---------------------------------------------------------------- GEMM body
// C[128 x BN] = sum_k A[m][k]*B[n][k]  (K-major bf16 hi/lo planes).
// K-chunk 64 (128B rows, SW128), NSTAGE pipeline, ONE __syncthreads per chunk.
template<int BN, int KDIM, int NSTAGE, bool SPLIT_OUT>
__device__ __forceinline__ void gemm_body(
    const bf16* __restrict__ Ahi, const bf16* __restrict__ Alo, int64_t aB, int64_t lda,
    const bf16* __restrict__ Bhi, const bf16* __restrict__ Blo, int64_t bB, int64_t ldb,
    float* __restrict__ Cf, bf16* __restrict__ Chi, bf16* __restrict__ Clo,
    int64_t cB, int64_t ldc, float scale, char* smem)
{
    constexpr int NC    = KDIM / 64;
    constexpr int ASTG  = 128 * 128;            // bytes per A plane per stage
    constexpr int BSTG  = BN * 128;
    constexpr int STG   = 2 * ASTG + 2 * BSTG;
    constexpr int NWN   = BN / 4;
    constexpr int NFRAG = BN / 32;

    const uint32_t sb = smem_u32(smem);
    const int tid = threadIdx.x, lane = tid & 31, wid = tid >> 5;
    const int wm = wid >> 2, wn = wid & 3;

    float cf[4][NFRAG][4];
#pragma unroll
    for (int mf = 0; mf < 4; ++mf)
#pragma unroll
        for (int nf = 0; nf < NFRAG; ++nf)
#pragma unroll
            for (int q = 0; q < 4; ++q) cf[mf][nf][q] = 0.f;

    auto issue = [&](int c) {
        const uint32_t so = sb + (c % NSTAGE) * STG;
        const bf16* ah = Ahi + aB + c * 64;
        const bf16* al = Alo + aB + c * 64;
#pragma unroll
        for (int s = tid; s < 1024; s += 256) {             // A: 128 rows x 8 segs(16B)
            const int r = s >> 3, g = s & 7;
            const uint32_t sw = SWZ(r * 128 + g * 16);
            const int64_t go = (int64_t)r * lda + g * 8;
            cpa16(so + sw, ah + go);
            cpa16(so + ASTG + sw, al + go);
        }
        const bf16* bh = Bhi + bB + c * 64;
        const bf16* bl = Blo + bB + c * 64;
#pragma unroll
        for (int s = tid; s < BN * 8; s += 256) {           // B: BN rows x 8 segs
            const int r = s >> 3, g = s & 7;
            const uint32_t sw = SWZ(r * 128 + g * 16);
            const int64_t go = (int64_t)r * ldb + g * 8;
            cpa16(so + 2 * ASTG + sw, bh + go);
            cpa16(so + 2 * ASTG + BSTG + sw, bl + go);
        }
        asm volatile("cp.async.commit_group;" ::: "memory");
    };

    const int l8 = lane & 7, sub = lane >> 3;
    const int arow = wm * 64 + l8 + (sub & 1) * 8;          // + mf*16
    const int asegsel = sub >> 1;
    const int brow = wn * NWN + l8 + (sub >> 1) * 8;        // + nb*8
    const int bsegsel = sub & 1;

    auto compute = [&](int c) {
        const uint32_t sA  = sb + (c % NSTAGE) * STG;
        const uint32_t sBh = sA + 2 * ASTG;
#pragma unroll
        for (int kk = 0; kk < 4; ++kk) {
            uint32_t af[2][4][4];
#pragma unroll
            for (int mf = 0; mf < 4; ++mf) {
                const uint32_t ad = sA + SWZ((arow + mf * 16) * 128 + (kk * 2 + asegsel) * 16);
                ldsm4(af[0][mf], ad);
                ldsm4(af[1][mf], ad + ASTG);
            }
            uint32_t bfr[2][NFRAG][2];
#pragma unroll
            for (int nb = 0; nb < NFRAG; nb += 2) {
                const uint32_t bd = SWZ((brow + nb * 8) * 128 + (kk * 2 + bsegsel) * 16);
                uint32_t t[4];
                ldsm4(t, sBh + bd);
                bfr[0][nb][0] = t[0]; bfr[0][nb][1] = t[1];
                bfr[0][nb + 1][0] = t[2]; bfr[0][nb + 1][1] = t[3];
                ldsm4(t, sBh + BSTG + bd);
                bfr[1][nb][0] = t[0]; bfr[1][nb][1] = t[1];
                bfr[1][nb + 1][0] = t[2]; bfr[1][nb + 1][1] = t[3];
            }
#pragma unroll
            for (int mf = 0; mf < 4; ++mf)
#pragma unroll
                for (int nf = 0; nf < NFRAG; ++nf) {
                    mma_bf16(cf[mf][nf], af[0][mf], bfr[0][nf]);   // hi*hi
                    mma_bf16(cf[mf][nf], af[0][mf], bfr[1][nf]);   // hi*lo
                    mma_bf16(cf[mf][nf], af[1][mf], bfr[0][nf]);   // lo*hi
                }
        }
    };

    // prologue: NSTAGE-1 chunks in flight
#pragma unroll
    for (int c = 0; c < NSTAGE - 1 && c < NC; ++c) issue(c);

    // steady state: wait -> sync -> issue next (or empty commit) -> compute
    for (int c = 0; c < NC; ++c) {
        asm volatile("cp.async.wait_group %0;" :: "n"(NSTAGE - 2) : "memory");
        __syncthreads();
        if (c + NSTAGE - 1 < NC) issue(c + NSTAGE - 1);
        else asm volatile("cp.async.commit_group;" ::: "memory");
        compute(c);
    }

    const int crow0 = wm * 64 + lane / 4;
    const int ccol0 = wn * NWN + (lane % 4) * 2;
#pragma unroll
    for (int mf = 0; mf < 4; ++mf)
#pragma unroll
        for (int nf = 0; nf < NFRAG; ++nf) {
            const int64_t o0 = cB + (int64_t)(crow0 + mf * 16) * ldc + ccol0 + nf * 8;
            const int64_t o1 = o0 + 8 * ldc;
            if constexpr (SPLIT_OUT) {
                unsigned short h0, l0, h1, l1;
                split2(cf[mf][nf][0] * scale, h0, l0);
                split2(cf[mf][nf][1] * scale, h1, l1);
                *(uint32_t*)&Chi[o0] = (uint32_t)h0 | ((uint32_t)h1 << 16);
                *(uint32_t*)&Clo[o0] = (uint32_t)l0 | ((uint32_t)l1 << 16);
                split2(cf[mf][nf][2] * scale, h0, l0);
                split2(cf[mf][nf][3] * scale, h1, l1);
                *(uint32_t*)&Chi[o1] = (uint32_t)h0 | ((uint32_t)h1 << 16);
                *(uint32_t*)&Clo[o1] = (uint32_t)l0 | ((uint32_t)l1 << 16);
            } else {
                *(float2*)&Cf[o0] = make_float2(cf[mf][nf][0], cf[mf][nf][1]);
                *(float2*)&Cf[o1] = make_float2(cf[mf][nf][2], cf[mf][nf][3]);
            }
        }
}

// ---------------------------------------------------------------- merged q/k/vt projections
// grid (8, 96): y in [0,32) -> q, [32,64) -> k, [64,96) -> vt (8 row-blocks x 4 batches)
__global__ __launch_bounds__(256)
void proj3_kernel(const bf16* __restrict__ xhi, const bf16* __restrict__ xlo,
                  const bf16* __restrict__ chi, const bf16* __restrict__ clo,
                  const bf16* __restrict__ wqh, const bf16* __restrict__ wql,
                  const bf16* __restrict__ wkh, const bf16* __restrict__ wkl,
                  bf16* __restrict__ qh, bf16* __restrict__ ql,
                  bf16* __restrict__ kh, bf16* __restrict__ kl,
                  bf16* __restrict__ vth, bf16* __restrict__ vtl)
{
    extern __shared__ char smem[];
    const int64_t M20 = 1 << 20;
    const int y = blockIdx.y, bx = blockIdx.x;
    const bf16 *Ah, *Al, *Bh, *Bl;
    bf16 *Ch, *Cl;
    int64_t aB, bB, cB;
    float scale;
    if (y < 32) {                   // q = 0.125 * x @ Wq^T-rows
        Ah = xhi; Al = xlo; Bh = wqh; Bl = wql; Ch = qh; Cl = ql; scale = 0.125f;
        aB = (int64_t)y * 131072;                    // y*128*1024
        bB = (int64_t)bx * 131072;
        cB = (int64_t)y * 131072 + bx * 128;
    } else if (y < 64) {            // k = ctx @ Wkv_k
        const int yy = y - 32;
        Ah = chi; Al = clo; Bh = wkh; Bl = wkl; Ch = kh; Cl = kl; scale = 1.f;
        aB = (int64_t)yy * 131072;
        bB = (int64_t)bx * 131072;
        cB = (int64_t)yy * 131072 + bx * 128;
    } else {                        // vt[b][h*64+vd][j] = Wkv_v^T @ ctx_b^T
        const int yy = y - 64, bt = yy >> 3, r = yy & 7;
        Ah = wkh + M20; Al = wkl + M20; Bh = chi; Bl = clo;
        Ch = vth; Cl = vtl; scale = 1.f;
        aB = (int64_t)r * 131072;
        bB = (int64_t)bt * M20 + (int64_t)bx * 131072;
        cB = (int64_t)bt * M20 + (int64_t)r * 131072 + bx * 128;
    }
    gemm_body<128, 1024, 3, true>(Ah, Al, aB, 1024, Bh, Bl, bB, 1024,
                                  nullptr, Ch, Cl, cB, 1024, scale, smem);
}

// ---------------------------------------------------------------- generic strided GEMM kernel
// Per-z offsets: (z>>4)*S1 + (z&15)*S2 elements.
template<int BN, int KDIM, int NSTAGE, bool SPLIT_OUT>
__global__ __launch_bounds__(256)
void hmma_gemm(const bf16* __restrict__ Ahi, const bf16* __restrict__ Alo,
               int64_t aS1, int64_t aS2, int64_t lda,
               const bf16* __restrict__ Bhi, const bf16* __restrict__ Blo,
               int64_t bS1, int64_t bS2, int64_t ldb,
               float* __restrict__ Cf, bf16* __restrict__ Chi, bf16* __restrict__ Clo,
               int64_t cS1, int64_t cS2, int64_t ldc, float scale)
{
    extern __shared__ char smem[];
    const int z = blockIdx.z;
    const int64_t aB = (int64_t)(z >> 4) * aS1 + (int64_t)(z & 15) * aS2
                     + (int64_t)blockIdx.y * 128 * lda;
    const int64_t bB = (int64_t)(z >> 4) * bS1 + (int64_t)(z & 15) * bS2
                     + (int64_t)blockIdx.x * BN * ldb;
    const int64_t cB = (int64_t)(z >> 4) * cS1 + (int64_t)(z & 15) * cS2
                     + (int64_t)blockIdx.y * 128 * ldc + (int64_t)blockIdx.x * BN;
    gemm_body<BN, KDIM, NSTAGE, SPLIT_OUT>(Ahi, Alo, aB, lda, Bhi, Blo, bB, ldb,
                                           Cf, Chi, Clo, cB, ldc, scale, smem);
}

// ---------------------------------------------------------------- softmax + talking heads + LN
__global__ __launch_bounds__(256) void softtalk_kernel(
    const float* __restrict__ Wt, const float* __restrict__ gamma, const float* __restrict__ beta)
{
    extern __shared__ float sm[];        // [0:256) Wt, [256:272) gamma, [288:304) beta, rows @512
    float* rows = sm + 512;              // 16 rows x 1028
    const int tid = threadIdx.x;
    sm[tid] = Wt[tid];
    if (tid < 16) { sm[256 + tid] = gamma[tid]; sm[288 + tid] = beta[tid]; }
    const int b = blockIdx.x >> 10, i = blockIdx.x & 1023;
    const size_t base = ((size_t)b * 16) << 20;
    const size_t irow = (size_t)i * 1024;
#pragma unroll
    for (int h = 0; h < 16; ++h)
        *(float4*)(rows + h * 1028 + tid * 4) =
            *(const float4*)(g_w + base + ((size_t)h << 20) + irow + tid * 4);
    __syncthreads();

    const int wid = tid >> 5, lane = tid & 31;
#pragma unroll
    for (int rr = wid; rr < 16; rr += 8) {
        float* r = rows + rr * 1028;
        float mx = -1e30f;
        for (int j = lane; j < 1024; j += 32) mx = fmaxf(mx, r[j]);
#pragma unroll
        for (int o = 16; o; o >>= 1) mx = fmaxf(mx, __shfl_xor_sync(~0u, mx, o));
        float s = 0.f;
        for (int j = lane; j < 1024; j += 32) { float e = __expf(r[j] - mx); r[j] = e; s += e; }
#pragma unroll
        for (int o = 16; o; o >>= 1) s += __shfl_xor_sync(~0u, s, o);
        const float inv = 1.f / s;
        for (int j = lane; j < 1024; j += 32) r[j] *= inv;
    }
    __syncthreads();

#pragma unroll
    for (int jj = 0; jj < 4; ++jj) {
        const int j = tid + jj * 256;
        float o[16];
#pragma unroll
        for (int g = 0; g < 16; ++g) o[g] = 0.f;
#pragma unroll
        for (int h = 0; h < 16; ++h) {
            const float v = rows[h * 1028 + j];
#pragma unroll
            for (int g = 0; g < 16; ++g) o[g] = fmaf(v, sm[h * 16 + g], o[g]);
        }
        float mu = 0.f;
#pragma unroll
        for (int g = 0; g < 16; ++g) mu += o[g];
        mu *= 0.0625f;
        float var = 0.f;
#pragma unroll
        for (int g = 0; g < 16; ++g) { const float dd = o[g] - mu; var = fmaf(dd, dd, var); }
        var *= 0.0625f;
        const float rstd = rsqrtf(var + 1e-5f);
#pragma unroll
        for (int g = 0; g < 16; ++g) {
            const float val = (o[g] - mu) * rstd * sm[256 + g] + sm[288 + g];
            unsigned short h16, l16;
            split2(val, h16, l16);
            const size_t oo = base + ((size_t)g << 20) + irow + j;
            g_whi[oo] = __ushort_as_bfloat16(h16);
            g_wlo[oo] = __ushort_as_bfloat16(l16);
        }
    }
}

// ---------------------------------------------------------------- launch
extern "C" void kernel_launch(void* const* d_in, const int* in_sizes, int n_in,
                              void* d_out, int out_size) {
    (void)in_sizes; (void)n_in; (void)out_size;
    const float* x   = (const float*)d_in[0];
    const float* ctx = (const float*)d_in[1];
    const float* Wq  = (const float*)d_in[2];
    const float* Wkv = (const float*)d_in[3];
    const float* Wt  = (const float*)d_in[4];
    const float* gm  = (const float*)d_in[5];
    const float* bt  = (const float*)d_in[6];
    float* out = (float*)d_out;

    bf16 *xhi, *xlo, *chi, *clo, *wqh, *wql, *wkh, *wkl;
    bf16 *qh, *ql, *kh, *kl, *vth, *vtl, *whi, *wlo;
    float* gw;
    cudaGetSymbolAddress((void**)&xhi, g_xhi);   cudaGetSymbolAddress((void**)&xlo, g_xlo);
    cudaGetSymbolAddress((void**)&chi, g_chi);   cudaGetSymbolAddress((void**)&clo, g_clo);
    cudaGetSymbolAddress((void**)&wqh, g_wqhi);  cudaGetSymbolAddress((void**)&wql, g_wqlo);
    cudaGetSymbolAddress((void**)&wkh, g_wkhi);  cudaGetSymbolAddress((void**)&wkl, g_wklo);
    cudaGetSymbolAddress((void**)&qh,  g_qhi);   cudaGetSymbolAddress((void**)&ql,  g_qlo);
    cudaGetSymbolAddress((void**)&kh,  g_khi);   cudaGetSymbolAddress((void**)&kl,  g_klo);
    cudaGetSymbolAddress((void**)&vth, g_vthi);  cudaGetSymbolAddress((void**)&vtl, g_vtlo);
    cudaGetSymbolAddress((void**)&whi, g_whi);   cudaGetSymbolAddress((void**)&wlo, g_wlo);
    cudaGetSymbolAddress((void**)&gw,  g_w);

    // stage: BN=128 -> 64KB, BN=64 -> 48KB
    constexpr int SMEM_PROJ = 3 * 65536;    // 196608 (3-stage)
    constexpr int SMEM_DOT  = 2 * 65536;    // 131072 (K=64 -> single chunk)
    constexpr int SMEM_ATT  = 3 * 49152;    // 147456 (3-stage)
    constexpr int SST       = (512 + 16 * 1028) * 4;
    cudaFuncSetAttribute(proj3_kernel,                   cudaFuncAttributeMaxDynamicSharedMemorySize, SMEM_PROJ);
    cudaFuncSetAttribute(hmma_gemm<128,  64, 2, false>,  cudaFuncAttributeMaxDynamicSharedMemorySize, SMEM_DOT);
    cudaFuncSetAttribute(hmma_gemm< 64, 1024, 3, false>, cudaFuncAttributeMaxDynamicSharedMemorySize, SMEM_ATT);
    cudaFuncSetAttribute(softtalk_kernel,                cudaFuncAttributeMaxDynamicSharedMemorySize, SST);

    const int64_t M20 = 1 << 20;

    split_kernel<<<4096, 256>>>(x, xhi, xlo);
    split_kernel<<<4096, 256>>>(ctx, chi, clo);
    tsplit_kernel<<<dim3(32, 32), dim3(32, 8)>>>(Wq,  wqh, wql, 1024, 1024);
    tsplit_kernel<<<dim3(64, 32), dim3(32, 8)>>>(Wkv, wkh, wkl, 1024, 2048);

    // merged q/k/vt projections (768 CTAs in one wave-train)
    proj3_kernel<<<dim3(8, 96), 256, SMEM_PROJ>>>(
        xhi, xlo, chi, clo, wqh, wql, wkh, wkl, qh, ql, kh, kl, vth, vtl);

    // dots: per (b,h) 1024 x 1024 x 64 -> g_w fp32
    hmma_gemm<128, 64, 2, false><<<dim3(8, 8, 64), 256, SMEM_DOT>>>(
        qh, ql, M20, 64, 1024,  kh, kl, M20, 64, 1024,
        gw, nullptr, nullptr, 16 * M20, M20, 1024, 1.f);
    // softmax + talking + LN -> g_whi/g_wlo
    softtalk_kernel<<<4096, 256, SST>>>(Wt, gm, bt);
    // out = w @ v : per (b,h) 1024 x 64 x 1024, scattered into d_out
    hmma_gemm<64, 1024, 3, false><<<dim3(1, 8, 64), 256, SMEM_ATT>>>(
        whi, wlo, 16 * M20, M20, 1024,  vth, vtl, M20, 65536, 1024,
        out, nullptr, nullptr, M20, 64, 1024, 1.f);
}

// round 13
// speedup vs baseline: 1.0560x; 1.0541x over previous
#include <cuda_runtime.h>
#include <cuda_bf16.h>
#include <cstdint>

using bf16 = __nv_bfloat16;

// CrossAttention B=4, N=M=1024, DIM=1024, H=16, d=vd=64.
// HMMA (mma.sync bf16) with bf16x3 split precision, fp32 accumulators.
// R13: exact R10 GEMM mainloop (2-stage, K-chunk 64, SW128, two syncs/chunk);
//      single change vs R10: q/k/vt projections merged into ONE launch.

// ---------------------------------------------------------------- scratch
__device__ __align__(16) bf16 g_xhi[4194304], g_xlo[4194304];     // x split
__device__ __align__(16) bf16 g_chi[4194304], g_clo[4194304];     // ctx split
__device__ __align__(16) bf16 g_wqhi[1048576], g_wqlo[1048576];   // Wq^T  [out][in]
__device__ __align__(16) bf16 g_wkhi[2097152], g_wklo[2097152];   // Wkv^T [out][in]
__device__ __align__(16) bf16 g_qhi[4194304], g_qlo[4194304];     // q*0.125 [b*N+i][h*64+d]
__device__ __align__(16) bf16 g_khi[4194304], g_klo[4194304];     // k       [b*M+j][h*64+d]
__device__ __align__(16) bf16 g_vthi[4194304], g_vtlo[4194304];   // v^T [b][h*64+vd][j]
__device__ float g_w[67108864];                                   // scores fp32 [b,h,i,j]
__device__ __align__(16) bf16 g_whi[67108864], g_wlo[67108864];   // post-softtalk w split

// ---------------------------------------------------------------- helpers
__device__ __forceinline__ uint32_t smem_u32(const void* p) {
    uint32_t a;
    asm("{ .reg .u64 t; cvta.to.shared.u64 t, %1; cvt.u32.u64 %0, t; }" : "=r"(a) : "l"(p));
    return a;
}
__device__ __forceinline__ void split2(float v, unsigned short& h, unsigned short& l) {
    bf16 hb = __float2bfloat16(v);
    h = __bfloat16_as_ushort(hb);
    l = __bfloat16_as_ushort(__float2bfloat16(v - __bfloat162float(hb)));
}
#define SWZ(x) ((x) ^ (((x) >> 3) & 0x70))

__device__ __forceinline__ void cpa16(uint32_t dst, const void* src) {
    asm volatile("cp.async.cg.shared.global [%0], [%1], 16;" :: "r"(dst), "l"(src));
}
__device__ __forceinline__ void ldsm4(uint32_t r[4], uint32_t addr) {
    asm volatile("ldmatrix.sync.aligned.m8n8.x4.shared.b16 {%0,%1,%2,%3}, [%4];"
                 : "=r"(r[0]), "=r"(r[1]), "=r"(r[2]), "=r"(r[3]) : "r"(addr));
}
__device__ __forceinline__ void mma_bf16(float c[4], const uint32_t a[4], const uint32_t b[2]) {
    asm volatile(
        "mma.sync.aligned.m16n8k16.row.col.f32.bf16.bf16.f32 "
        "{%0,%1,%2,%3}, {%4,%5,%6,%7}, {%8,%9}, {%0,%1,%2,%3};"
        : "+f"(c[0]), "+f"(c[1]), "+f"(c[2]), "+f"(c[3])
        : "r"(a[0]), "r"(a[1]), "r"(a[2]), "r"(a[3]), "r"(b[0]), "r"(b[1]));
}

// ---------------------------------------------------------------- prep kernels
__global__ __launch_bounds__(256) void split_kernel(const float* __restrict__ s,
                                                    bf16* __restrict__ hi, bf16* __restrict__ lo) {
    size_t i = (size_t)blockIdx.x * 256 + threadIdx.x;
    float4 v = ((const float4*)s)[i];
    unsigned short hh[4], ll[4];
    split2(v.x, hh[0], ll[0]); split2(v.y, hh[1], ll[1]);
    split2(v.z, hh[2], ll[2]); split2(v.w, hh[3], ll[3]);
    ((uint2*)hi)[i] = *(uint2*)hh;
    ((uint2*)lo)[i] = *(uint2*)ll;
}

__global__ void tsplit_kernel(const float* __restrict__ s, bf16* __restrict__ hi,
                              bf16* __restrict__ lo, int R, int C) {
    __shared__ float t[32][33];
    const int c0 = blockIdx.x * 32, r0 = blockIdx.y * 32;
    const int tx = threadIdx.x, ty = threadIdx.y;
#pragma unroll
    for (int k = 0; k < 4; ++k)
        t[ty + 8 * k][tx] = s[(size_t)(r0 + ty + 8 * k) * C + c0 + tx];
    __syncthreads();
#pragma unroll
    for (int k = 0; k < 4; ++k) {
        unsigned short h, l;
        split2(t[tx][ty + 8 * k], h, l);
        const size_t o = (size_t)(c0 + ty + 8 * k) * R + r0 + tx;
        hi[o] = __ushort_as_bfloat16(h);
        lo[o] = __ushort_as_bfloat16(l);
    }
}

// ---------------------------------------------------------------- GEMM body (EXACT R10 loop)
// C[128 x BN] = sum_k A[m][k]*B[n][k]  (K-major bf16 hi/lo planes).
// K-chunk 64 (128B rows, SW128), 2-stage, wait(1)/wait(0), two syncs per chunk.
template<int BN, int KDIM, bool SPLIT_OUT>
__device__ __forceinline__ void gemm_body(
    const bf16* __restrict__ Ahi, const bf16* __restrict__ Alo, int64_t aB, int64_t lda,
    const bf16* __restrict__ Bhi, const bf16* __restrict__ Blo, int64_t bB, int64_t ldb,
    float* __restrict__ Cf, bf16* __restrict__ Chi, bf16* __restrict__ Clo,
    int64_t cB, int64_t ldc, float scale, char* smem)
{
    constexpr int NC    = KDIM / 64;
    constexpr int ASTG  = 128 * 128;            // bytes per A plane per stage
    constexpr int BSTG  = BN * 128;
    constexpr int STAGE = 2 * ASTG + 2 * BSTG;
    constexpr int NWN   = BN / 4;               // warp n-extent (32 or 16)
    constexpr int NFRAG = BN / 32;              // n-frags per warp (4 or 2)

    const uint32_t sb = smem_u32(smem);
    const int tid = threadIdx.x, lane = tid & 31, wid = tid >> 5;
    const int wm = wid >> 2, wn = wid & 3;

    float cf[4][NFRAG][4];
#pragma unroll
    for (int mf = 0; mf < 4; ++mf)
#pragma unroll
        for (int nf = 0; nf < NFRAG; ++nf)
#pragma unroll
            for (int q = 0; q < 4; ++q) cf[mf][nf][q] = 0.f;

    auto issue = [&](int c) {
        const uint32_t so = sb + (c & 1) * STAGE;
        const bf16* ah = Ahi + aB + c * 64;
        const bf16* al = Alo + aB + c * 64;
#pragma unroll
        for (int s = tid; s < 1024; s += 256) {             // A: 128 rows x 8 segs(16B)
            const int r = s >> 3, g = s & 7;
            const uint32_t sw = SWZ(r * 128 + g * 16);
            const int64_t go = (int64_t)r * lda + g * 8;
            cpa16(so + sw, ah + go);
            cpa16(so + ASTG + sw, al + go);
        }
        const bf16* bh = Bhi + bB + c * 64;
        const bf16* bl = Blo + bB + c * 64;
#pragma unroll
        for (int s = tid; s < BN * 8; s += 256) {           // B: BN rows x 8 segs
            const int r = s >> 3, g = s & 7;
            const uint32_t sw = SWZ(r * 128 + g * 16);
            const int64_t go = (int64_t)r * ldb + g * 8;
            cpa16(so + 2 * ASTG + sw, bh + go);
            cpa16(so + 2 * ASTG + BSTG + sw, bl + go);
        }
        asm volatile("cp.async.commit_group;" ::: "memory");
    };

    const int l8 = lane & 7, sub = lane >> 3;
    const int arow = wm * 64 + l8 + (sub & 1) * 8;          // + mf*16
    const int asegsel = sub >> 1;
    const int brow = wn * NWN + l8 + (sub >> 1) * 8;        // + nb*8
    const int bsegsel = sub & 1;

    auto compute = [&](int c) {
        const uint32_t sA  = sb + (c & 1) * STAGE;
        const uint32_t sBh = sA + 2 * ASTG;
#pragma unroll
        for (int kk = 0; kk < 4; ++kk) {
            uint32_t af[2][4][4];
#pragma unroll
            for (int mf = 0; mf < 4; ++mf) {
                const uint32_t ad = sA + SWZ((arow + mf * 16) * 128 + (kk * 2 + asegsel) * 16);
                ldsm4(af[0][mf], ad);
                ldsm4(af[1][mf], ad + ASTG);
            }
            uint32_t bfr[2][NFRAG][2];
#pragma unroll
            for (int nb = 0; nb < NFRAG; nb += 2) {
                const uint32_t bd = SWZ((brow + nb * 8) * 128 + (kk * 2 + bsegsel) * 16);
                uint32_t t[4];
                ldsm4(t, sBh + bd);
                bfr[0][nb][0] = t[0]; bfr[0][nb][1] = t[1];
                bfr[0][nb + 1][0] = t[2]; bfr[0][nb + 1][1] = t[3];
                ldsm4(t, sBh + BSTG + bd);
                bfr[1][nb][0] = t[0]; bfr[1][nb][1] = t[1];
                bfr[1][nb + 1][0] = t[2]; bfr[1][nb + 1][1] = t[3];
            }
#pragma unroll
            for (int mf = 0; mf < 4; ++mf)
#pragma unroll
                for (int nf = 0; nf < NFRAG; ++nf) {
                    mma_bf16(cf[mf][nf], af[0][mf], bfr[0][nf]);   // hi*hi
                    mma_bf16(cf[mf][nf], af[0][mf], bfr[1][nf]);   // hi*lo
                    mma_bf16(cf[mf][nf], af[1][mf], bfr[0][nf]);   // lo*hi
                }
        }
    };

    issue(0);
    if (NC > 1) issue(1);
    for (int c = 0; c < NC; ++c) {
        if (c + 1 < NC) asm volatile("cp.async.wait_group 1;" ::: "memory");
        else            asm volatile("cp.async.wait_group 0;" ::: "memory");
        __syncthreads();
        compute(c);
        __syncthreads();
        if (c + 2 < NC) issue(c + 2);
    }

    const int crow0 = wm * 64 + lane / 4;
    const int ccol0 = wn * NWN + (lane % 4) * 2;
#pragma unroll
    for (int mf = 0; mf < 4; ++mf)
#pragma unroll
        for (int nf = 0; nf < NFRAG; ++nf) {
            const int64_t o0 = cB + (int64_t)(crow0 + mf * 16) * ldc + ccol0 + nf * 8;
            const int64_t o1 = o0 + 8 * ldc;
            if constexpr (SPLIT_OUT) {
                unsigned short h0, l0, h1, l1;
                split2(cf[mf][nf][0] * scale, h0, l0);
                split2(cf[mf][nf][1] * scale, h1, l1);
                *(uint32_t*)&Chi[o0] = (uint32_t)h0 | ((uint32_t)h1 << 16);
                *(uint32_t*)&Clo[o0] = (uint32_t)l0 | ((uint32_t)l1 << 16);
                split2(cf[mf][nf][2] * scale, h0, l0);
                split2(cf[mf][nf][3] * scale, h1, l1);
                *(uint32_t*)&Chi[o1] = (uint32_t)h0 | ((uint32_t)h1 << 16);
                *(uint32_t*)&Clo[o1] = (uint32_t)l0 | ((uint32_t)l1 << 16);
            } else {
                *(float2*)&Cf[o0] = make_float2(cf[mf][nf][0], cf[mf][nf][1]);
                *(float2*)&Cf[o1] = make_float2(cf[mf][nf][2], cf[mf][nf][3]);
            }
        }
}

// ---------------------------------------------------------------- merged q/k/vt projections
// grid (8, 96): y in [0,32) -> q, [32,64) -> k, [64,96) -> vt (4 batches x 8 row-blocks)
__global__ __launch_bounds__(256)
void proj3_kernel(const bf16* __restrict__ xhi, const bf16* __restrict__ xlo,
                  const bf16* __restrict__ chi, const bf16* __restrict__ clo,
                  const bf16* __restrict__ wqh, const bf16* __restrict__ wql,
                  const bf16* __restrict__ wkh, const bf16* __restrict__ wkl,
                  bf16* __restrict__ qh, bf16* __restrict__ ql,
                  bf16* __restrict__ kh, bf16* __restrict__ kl,
                  bf16* __restrict__ vth, bf16* __restrict__ vtl)
{
    extern __shared__ char smem[];
    const int64_t M20 = 1 << 20;
    const int y = blockIdx.y, bx = blockIdx.x;
    const bf16 *Ah, *Al, *Bh, *Bl;
    bf16 *Ch, *Cl;
    int64_t aB, bB, cB;
    float scale;
    if (y < 32) {                   // q = 0.125 * x @ Wq
        Ah = xhi; Al = xlo; Bh = wqh; Bl = wql; Ch = qh; Cl = ql; scale = 0.125f;
        aB = (int64_t)y * 131072;                    // y*128*1024
        bB = (int64_t)bx * 131072;
        cB = (int64_t)y * 131072 + bx * 128;
    } else if (y < 64) {            // k = ctx @ Wkv_k
        const int yy = y - 32;
        Ah = chi; Al = clo; Bh = wkh; Bl = wkl; Ch = kh; Cl = kl; scale = 1.f;
        aB = (int64_t)yy * 131072;
        bB = (int64_t)bx * 131072;
        cB = (int64_t)yy * 131072 + bx * 128;
    } else {                        // vt[b][h*64+vd][j] = Wkv_v^T @ ctx_b^T
        const int yy = y - 64, bt = yy >> 3, r = yy & 7;
        Ah = wkh + M20; Al = wkl + M20; Bh = chi; Bl = clo;
        Ch = vth; Cl = vtl; scale = 1.f;
        aB = (int64_t)r * 131072;
        bB = (int64_t)bt * M20 + (int64_t)bx * 131072;
        cB = (int64_t)bt * M20 + (int64_t)r * 131072 + bx * 128;
    }
    gemm_body<128, 1024, true>(Ah, Al, aB, 1024, Bh, Bl, bB, 1024,
                               nullptr, Ch, Cl, cB, 1024, scale, smem);
}

// ---------------------------------------------------------------- generic strided GEMM kernel
// Per-z offsets: (z>>4)*S1 + (z&15)*S2 elements.
template<int BN, int KDIM, bool SPLIT_OUT>
__global__ __launch_bounds__(256)
void hmma_gemm(const bf16* __restrict__ Ahi, const bf16* __restrict__ Alo,
               int64_t aS1, int64_t aS2, int64_t lda,
               const bf16* __restrict__ Bhi, const bf16* __restrict__ Blo,
               int64_t bS1, int64_t bS2, int64_t ldb,
               float* __restrict__ Cf, bf16* __restrict__ Chi, bf16* __restrict__ Clo,
               int64_t cS1, int64_t cS2, int64_t ldc, float scale)
{
    extern __shared__ char smem[];
    const int z = blockIdx.z;
    const int64_t aB = (int64_t)(z >> 4) * aS1 + (int64_t)(z & 15) * aS2
                     + (int64_t)blockIdx.y * 128 * lda;
    const int64_t bB = (int64_t)(z >> 4) * bS1 + (int64_t)(z & 15) * bS2
                     + (int64_t)blockIdx.x * BN * ldb;
    const int64_t cB = (int64_t)(z >> 4) * cS1 + (int64_t)(z & 15) * cS2
                     + (int64_t)blockIdx.y * 128 * ldc + (int64_t)blockIdx.x * BN;
    gemm_body<BN, KDIM, SPLIT_OUT>(Ahi, Alo, aB, lda, Bhi, Blo, bB, ldb,
                                   Cf, Chi, Clo, cB, ldc, scale, smem);
}

// ---------------------------------------------------------------- softmax + talking heads + LN
__global__ __launch_bounds__(256) void softtalk_kernel(
    const float* __restrict__ Wt, const float* __restrict__ gamma, const float* __restrict__ beta)
{
    extern __shared__ float sm[];        // [0:256) Wt, [256:272) gamma, [288:304) beta, rows @512
    float* rows = sm + 512;              // 16 rows x 1028
    const int tid = threadIdx.x;
    sm[tid] = Wt[tid];
    if (tid < 16) { sm[256 + tid] = gamma[tid]; sm[288 + tid] = beta[tid]; }
    const int b = blockIdx.x >> 10, i = blockIdx.x & 1023;
    const size_t base = ((size_t)b * 16) << 20;
    const size_t irow = (size_t)i * 1024;
#pragma unroll
    for (int h = 0; h < 16; ++h)
        *(float4*)(rows + h * 1028 + tid * 4) =
            *(const float4*)(g_w + base + ((size_t)h << 20) + irow + tid * 4);
    __syncthreads();

    const int wid = tid >> 5, lane = tid & 31;
#pragma unroll
    for (int rr = wid; rr < 16; rr += 8) {
        float* r = rows + rr * 1028;
        float mx = -1e30f;
        for (int j = lane; j < 1024; j += 32) mx = fmaxf(mx, r[j]);
#pragma unroll
        for (int o = 16; o; o >>= 1) mx = fmaxf(mx, __shfl_xor_sync(~0u, mx, o));
        float s = 0.f;
        for (int j = lane; j < 1024; j += 32) { float e = __expf(r[j] - mx); r[j] = e; s += e; }
#pragma unroll
        for (int o = 16; o; o >>= 1) s += __shfl_xor_sync(~0u, s, o);
        const float inv = 1.f / s;
        for (int j = lane; j < 1024; j += 32) r[j] *= inv;
    }
    __syncthreads();

#pragma unroll
    for (int jj = 0; jj < 4; ++jj) {
        const int j = tid + jj * 256;
        float o[16];
#pragma unroll
        for (int g = 0; g < 16; ++g) o[g] = 0.f;
#pragma unroll
        for (int h = 0; h < 16; ++h) {
            const float v = rows[h * 1028 + j];
#pragma unroll
            for (int g = 0; g < 16; ++g) o[g] = fmaf(v, sm[h * 16 + g], o[g]);
        }
        float mu = 0.f;
#pragma unroll
        for (int g = 0; g < 16; ++g) mu += o[g];
        mu *= 0.0625f;
        float var = 0.f;
#pragma unroll
        for (int g = 0; g < 16; ++g) { const float dd = o[g] - mu; var = fmaf(dd, dd, var); }
        var *= 0.0625f;
        const float rstd = rsqrtf(var + 1e-5f);
#pragma unroll
        for (int g = 0; g < 16; ++g) {
            const float val = (o[g] - mu) * rstd * sm[256 + g] + sm[288 + g];
            unsigned short h16, l16;
            split2(val, h16, l16);
            const size_t oo = base + ((size_t)g << 20) + irow + j;
            g_whi[oo] = __ushort_as_bfloat16(h16);
            g_wlo[oo] = __ushort_as_bfloat16(l16);
        }
    }
}

// ---------------------------------------------------------------- launch
extern "C" void kernel_launch(void* const* d_in, const int* in_sizes, int n_in,
                              void* d_out, int out_size) {
    (void)in_sizes; (void)n_in; (void)out_size;
    const float* x   = (const float*)d_in[0];
    const float* ctx = (const float*)d_in[1];
    const float* Wq  = (const float*)d_in[2];
    const float* Wkv = (const float*)d_in[3];
    const float* Wt  = (const float*)d_in[4];
    const float* gm  = (const float*)d_in[5];
    const float* bt  = (const float*)d_in[6];
    float* out = (float*)d_out;

    bf16 *xhi, *xlo, *chi, *clo, *wqh, *wql, *wkh, *wkl;
    bf16 *qh, *ql, *kh, *kl, *vth, *vtl, *whi, *wlo;
    float* gw;
    cudaGetSymbolAddress((void**)&xhi, g_xhi);   cudaGetSymbolAddress((void**)&xlo, g_xlo);
    cudaGetSymbolAddress((void**)&chi, g_chi);   cudaGetSymbolAddress((void**)&clo, g_clo);
    cudaGetSymbolAddress((void**)&wqh, g_wqhi);  cudaGetSymbolAddress((void**)&wql, g_wqlo);
    cudaGetSymbolAddress((void**)&wkh, g_wkhi);  cudaGetSymbolAddress((void**)&wkl, g_wklo);
    cudaGetSymbolAddress((void**)&qh,  g_qhi);   cudaGetSymbolAddress((void**)&ql,  g_qlo);
    cudaGetSymbolAddress((void**)&kh,  g_khi);   cudaGetSymbolAddress((void**)&kl,  g_klo);
    cudaGetSymbolAddress((void**)&vth, g_vthi);  cudaGetSymbolAddress((void**)&vtl, g_vtlo);
    cudaGetSymbolAddress((void**)&whi, g_whi);   cudaGetSymbolAddress((void**)&wlo, g_wlo);
    cudaGetSymbolAddress((void**)&gw,  g_w);

    // R10 stage sizes: BN=128 -> 2x64KB, BN=64 -> 2x48KB
    constexpr int SMEM_128 = 2 * (2 * 16384 + 2 * 16384);   // 131072
    constexpr int SMEM_DOT = (2 * 16384 + 2 * 16384);       // 65536 (K=64, single chunk)
    constexpr int SMEM_64  = 2 * (2 * 16384 + 2 * 8192);    // 98304
    constexpr int SST      = (512 + 16 * 1028) * 4;
    cudaFuncSetAttribute(proj3_kernel,               cudaFuncAttributeMaxDynamicSharedMemorySize, SMEM_128);
    cudaFuncSetAttribute(hmma_gemm<128,  64, false>, cudaFuncAttributeMaxDynamicSharedMemorySize, SMEM_DOT);
    cudaFuncSetAttribute(hmma_gemm< 64, 1024, false>, cudaFuncAttributeMaxDynamicSharedMemorySize, SMEM_64);
    cudaFuncSetAttribute(softtalk_kernel,            cudaFuncAttributeMaxDynamicSharedMemorySize, SST);

    const int64_t M20 = 1 << 20;

    split_kernel<<<4096, 256>>>(x, xhi, xlo);
    split_kernel<<<4096, 256>>>(ctx, chi, clo);
    tsplit_kernel<<<dim3(32, 32), dim3(32, 8)>>>(Wq,  wqh, wql, 1024, 1024);
    tsplit_kernel<<<dim3(64, 32), dim3(32, 8)>>>(Wkv, wkh, wkl, 1024, 2048);

    // merged q/k/vt projections: 768 CTAs, one wave-train (was 3 launches x 256 CTAs)
    proj3_kernel<<<dim3(8, 96), 256, SMEM_128>>>(
        xhi, xlo, chi, clo, wqh, wql, wkh, wkl, qh, ql, kh, kl, vth, vtl);

    // dots: per (b,h) 1024 x 1024 x 64 -> g_w fp32
    hmma_gemm<128, 64, false><<<dim3(8, 8, 64), 256, SMEM_DOT>>>(
        qh, ql, M20, 64, 1024,  kh, kl, M20, 64, 1024,
        gw, nullptr, nullptr, 16 * M20, M20, 1024, 1.f);
    // softmax + talking + LN -> g_whi/g_wlo
    softtalk_kernel<<<4096, 256, SST>>>(Wt, gm, bt);
    // out = w @ v : per (b,h) 1024 x 64 x 1024, scattered into d_out
    hmma_gemm<64, 1024, false><<<dim3(1, 8, 64), 256, SMEM_64>>>(
        whi, wlo, 16 * M20, M20, 1024,  vth, vtl, M20, 65536, 1024,
        out, nullptr, nullptr, M20, 64, 1024, 1.f);
}

// round 14
// speedup vs baseline: 1.0760x; 1.0190x over previous
#include <cuda_runtime.h>
#include <cuda_bf16.h>
#include <cstdint>

using bf16 = __nv_bfloat16;

// CrossAttention B=4, N=M=1024, DIM=1024, H=16, d=vd=64.
// HMMA (mma.sync bf16) with bf16x3 split precision, fp32 accumulators.
// R14: R13 + larger warp tiles for fragment reuse:
//   proj:  CTA 128x256, warp 64x64 (85 B smem per mma, was 128)
//   attnv: CTA 256x64,  warp 64x32 (128 B/mma, was 213)
//   dots:  unchanged (DRAM-write bound)
// Mainloop shape is exactly R10/R13 (2-stage, two syncs) — proven load-bearing.

// ---------------------------------------------------------------- scratch
__device__ __align__(16) bf16 g_xhi[4194304], g_xlo[4194304];     // x split
__device__ __align__(16) bf16 g_chi[4194304], g_clo[4194304];     // ctx split
__device__ __align__(16) bf16 g_wqhi[1048576], g_wqlo[1048576];   // Wq^T  [out][in]
__device__ __align__(16) bf16 g_wkhi[2097152], g_wklo[2097152];   // Wkv^T [out][in]
__device__ __align__(16) bf16 g_qhi[4194304], g_qlo[4194304];     // q*0.125 [b*N+i][h*64+d]
__device__ __align__(16) bf16 g_khi[4194304], g_klo[4194304];     // k       [b*M+j][h*64+d]
__device__ __align__(16) bf16 g_vthi[4194304], g_vtlo[4194304];   // v^T [b][h*64+vd][j]
__device__ float g_w[67108864];                                   // scores fp32 [b,h,i,j]
__device__ __align__(16) bf16 g_whi[67108864], g_wlo[67108864];   // post-softtalk w split

// ---------------------------------------------------------------- helpers
__device__ __forceinline__ uint32_t smem_u32(const void* p) {
    uint32_t a;
    asm("{ .reg .u64 t; cvta.to.shared.u64 t, %1; cvt.u32.u64 %0, t; }" : "=r"(a) : "l"(p));
    return a;
}
__device__ __forceinline__ void split2(float v, unsigned short& h, unsigned short& l) {
    bf16 hb = __float2bfloat16(v);
    h = __bfloat16_as_ushort(hb);
    l = __bfloat16_as_ushort(__float2bfloat16(v - __bfloat162float(hb)));
}
#define SWZ(x) ((x) ^ (((x) >> 3) & 0x70))

__device__ __forceinline__ void cpa16(uint32_t dst, const void* src) {
    asm volatile("cp.async.cg.shared.global [%0], [%1], 16;" :: "r"(dst), "l"(src));
}
__device__ __forceinline__ void ldsm4(uint32_t r[4], uint32_t addr) {
    asm volatile("ldmatrix.sync.aligned.m8n8.x4.shared.b16 {%0,%1,%2,%3}, [%4];"
                 : "=r"(r[0]), "=r"(r[1]), "=r"(r[2]), "=r"(r[3]) : "r"(addr));
}
__device__ __forceinline__ void mma_bf16(float c[4], const uint32_t a[4], const uint32_t b[2]) {
    asm volatile(
        "mma.sync.aligned.m16n8k16.row.col.f32.bf16.bf16.f32 "
        "{%0,%1,%2,%3}, {%4,%5,%6,%7}, {%8,%9}, {%0,%1,%2,%3};"
        : "+f"(c[0]), "+f"(c[1]), "+f"(c[2]), "+f"(c[3])
        : "r"(a[0]), "r"(a[1]), "r"(a[2]), "r"(a[3]), "r"(b[0]), "r"(b[1]));
}

// ---------------------------------------------------------------- prep kernels
__global__ __launch_bounds__(256) void split_kernel(const float* __restrict__ s,
                                                    bf16* __restrict__ hi, bf16* __restrict__ lo) {
    size_t i = (size_t)blockIdx.x * 256 + threadIdx.x;
    float4 v = ((const float4*)s)[i];
    unsigned short hh[4], ll[4];
    split2(v.x, hh[0], ll[0]); split2(v.y, hh[1], ll[1]);
    split2(v.z, hh[2], ll[2]); split2(v.w, hh[3], ll[3]);
    ((uint2*)hi)[i] = *(uint2*)hh;
    ((uint2*)lo)[i] = *(uint2*)ll;
}

__global__ void tsplit_kernel(const float* __restrict__ s, bf16* __restrict__ hi,
                              bf16* __restrict__ lo, int R, int C) {
    __shared__ float t[32][33];
    const int c0 = blockIdx.x * 32, r0 = blockIdx.y * 32;
    const int tx = threadIdx.x, ty = threadIdx.y;
#pragma unroll
    for (int k = 0; k < 4; ++k)
        t[ty + 8 * k][tx] = s[(size_t)(r0 + ty + 8 * k) * C + c0 + tx];
    __syncthreads();
#pragma unroll
    for (int k = 0; k < 4; ++k) {
        unsigned short h, l;
        split2(t[tx][ty + 8 * k], h, l);
        const size_t o = (size_t)(c0 + ty + 8 * k) * R + r0 + tx;
        hi[o] = __ushort_as_bfloat16(h);
        lo[o] = __ushort_as_bfloat16(l);
    }
}

// ---------------------------------------------------------------- GEMM body
// C[BM x BN] = sum_k A[m][k]*B[n][k]  (K-major bf16 hi/lo planes).
// Warp grid WGM x WGN (warp m-extent = BM/WGM = 64 always). NT = WGM*WGN*32 threads.
// K-chunk 64 (128B rows, SW128), 2-stage, wait(1)/wait(0), two syncs per chunk (R10 shape).
template<int BM, int BN, int WGM, int WGN, int KDIM, bool SPLIT_OUT>
__device__ __forceinline__ void gemm_body(
    const bf16* __restrict__ Ahi, const bf16* __restrict__ Alo, int64_t aB, int64_t lda,
    const bf16* __restrict__ Bhi, const bf16* __restrict__ Blo, int64_t bB, int64_t ldb,
    float* __restrict__ Cf, bf16* __restrict__ Chi, bf16* __restrict__ Clo,
    int64_t cB, int64_t ldc, float scale, char* smem)
{
    constexpr int NT    = WGM * WGN * 32;
    constexpr int NC    = KDIM / 64;
    constexpr int ASTG  = BM * 128;             // bytes per A plane per stage
    constexpr int BSTG  = BN * 128;
    constexpr int STAGE = 2 * ASTG + 2 * BSTG;
    constexpr int WN    = BN / WGN;             // warp n-extent (64 or 32 or 16)
    constexpr int NFRAG = WN / 8;
    static_assert(BM / WGM == 64, "warp m-extent must be 64");

    const uint32_t sb = smem_u32(smem);
    const int tid = threadIdx.x, lane = tid & 31, wid = tid >> 5;
    const int wm = wid / WGN, wn = wid % WGN;

    float cf[4][NFRAG][4];
#pragma unroll
    for (int mf = 0; mf < 4; ++mf)
#pragma unroll
        for (int nf = 0; nf < NFRAG; ++nf)
#pragma unroll
            for (int q = 0; q < 4; ++q) cf[mf][nf][q] = 0.f;

    auto issue = [&](int c) {
        const uint32_t so = sb + (c & 1) * STAGE;
        const bf16* ah = Ahi + aB + c * 64;
        const bf16* al = Alo + aB + c * 64;
#pragma unroll
        for (int s = tid; s < BM * 8; s += NT) {            // A: BM rows x 8 segs(16B)
            const int r = s >> 3, g = s & 7;
            const uint32_t sw = SWZ(r * 128 + g * 16);
            const int64_t go = (int64_t)r * lda + g * 8;
            cpa16(so + sw, ah + go);
            cpa16(so + ASTG + sw, al + go);
        }
        const bf16* bh = Bhi + bB + c * 64;
        const bf16* bl = Blo + bB + c * 64;
#pragma unroll
        for (int s = tid; s < BN * 8; s += NT) {            // B: BN rows x 8 segs
            const int r = s >> 3, g = s & 7;
            const uint32_t sw = SWZ(r * 128 + g * 16);
            const int64_t go = (int64_t)r * ldb + g * 8;
            cpa16(so + 2 * ASTG + sw, bh + go);
            cpa16(so + 2 * ASTG + BSTG + sw, bl + go);
        }
        asm volatile("cp.async.commit_group;" ::: "memory");
    };

    const int l8 = lane & 7, sub = lane >> 3;
    const int arow = wm * 64 + l8 + (sub & 1) * 8;          // + mf*16
    const int asegsel = sub >> 1;
    const int brow = wn * WN + l8 + (sub >> 1) * 8;         // + nb*8
    const int bsegsel = sub & 1;

    auto compute = [&](int c) {
        const uint32_t sA  = sb + (c & 1) * STAGE;
        const uint32_t sBh = sA + 2 * ASTG;
#pragma unroll
        for (int kk = 0; kk < 4; ++kk) {
            uint32_t af[2][4][4];
#pragma unroll
            for (int mf = 0; mf < 4; ++mf) {
                const uint32_t ad = sA + SWZ((arow + mf * 16) * 128 + (kk * 2 + asegsel) * 16);
                ldsm4(af[0][mf], ad);
                ldsm4(af[1][mf], ad + ASTG);
            }
            uint32_t bfr[2][NFRAG][2];
#pragma unroll
            for (int nb = 0; nb < NFRAG; nb += 2) {
                const uint32_t bd = SWZ((brow + nb * 8) * 128 + (kk * 2 + bsegsel) * 16);
                uint32_t t[4];
                ldsm4(t, sBh + bd);
                bfr[0][nb][0] = t[0]; bfr[0][nb][1] = t[1];
                bfr[0][nb + 1][0] = t[2]; bfr[0][nb + 1][1] = t[3];
                ldsm4(t, sBh + BSTG + bd);
                bfr[1][nb][0] = t[0]; bfr[1][nb][1] = t[1];
                bfr[1][nb + 1][0] = t[2]; bfr[1][nb + 1][1] = t[3];
            }
#pragma unroll
            for (int mf = 0; mf < 4; ++mf)
#pragma unroll
                for (int nf = 0; nf < NFRAG; ++nf) {
                    mma_bf16(cf[mf][nf], af[0][mf], bfr[0][nf]);   // hi*hi
                    mma_bf16(cf[mf][nf], af[0][mf], bfr[1][nf]);   // hi*lo
                    mma_bf16(cf[mf][nf], af[1][mf], bfr[0][nf]);   // lo*hi
                }
        }
    };

    issue(0);
    if (NC > 1) issue(1);
    for (int c = 0; c < NC; ++c) {
        if (c + 1 < NC) asm volatile("cp.async.wait_group 1;" ::: "memory");
        else            asm volatile("cp.async.wait_group 0;" ::: "memory");
        __syncthreads();
        compute(c);
        __syncthreads();
        if (c + 2 < NC) issue(c + 2);
    }

    const int crow0 = wm * 64 + lane / 4;
    const int ccol0 = wn * WN + (lane % 4) * 2;
#pragma unroll
    for (int mf = 0; mf < 4; ++mf)
#pragma unroll
        for (int nf = 0; nf < NFRAG; ++nf) {
            const int64_t o0 = cB + (int64_t)(crow0 + mf * 16) * ldc + ccol0 + nf * 8;
            const int64_t o1 = o0 + 8 * ldc;
            if constexpr (SPLIT_OUT) {
                unsigned short h0, l0, h1, l1;
                split2(cf[mf][nf][0] * scale, h0, l0);
                split2(cf[mf][nf][1] * scale, h1, l1);
                *(uint32_t*)&Chi[o0] = (uint32_t)h0 | ((uint32_t)h1 << 16);
                *(uint32_t*)&Clo[o0] = (uint32_t)l0 | ((uint32_t)l1 << 16);
                split2(cf[mf][nf][2] * scale, h0, l0);
                split2(cf[mf][nf][3] * scale, h1, l1);
                *(uint32_t*)&Chi[o1] = (uint32_t)h0 | ((uint32_t)h1 << 16);
                *(uint32_t*)&Clo[o1] = (uint32_t)l0 | ((uint32_t)l1 << 16);
            } else {
                *(float2*)&Cf[o0] = make_float2(cf[mf][nf][0], cf[mf][nf][1]);
                *(float2*)&Cf[o1] = make_float2(cf[mf][nf][2], cf[mf][nf][3]);
            }
        }
}

// ---------------------------------------------------------------- merged q/k/vt projections
// CTA tile 128x256, warp 64x64. grid (4, 96): y in [0,32) q, [32,64) k, [64,96) vt.
__global__ __launch_bounds__(256)
void proj3_kernel(const bf16* __restrict__ xhi, const bf16* __restrict__ xlo,
                  const bf16* __restrict__ chi, const bf16* __restrict__ clo,
                  const bf16* __restrict__ wqh, const bf16* __restrict__ wql,
                  const bf16* __restrict__ wkh, const bf16* __restrict__ wkl,
                  bf16* __restrict__ qh, bf16* __restrict__ ql,
                  bf16* __restrict__ kh, bf16* __restrict__ kl,
                  bf16* __restrict__ vth, bf16* __restrict__ vtl)
{
    extern __shared__ char smem[];
    const int64_t M20 = 1 << 20;
    const int y = blockIdx.y, bx = blockIdx.x;
    const bf16 *Ah, *Al, *Bh, *Bl;
    bf16 *Ch, *Cl;
    int64_t aB, bB, cB;
    float scale;
    if (y < 32) {                   // q = 0.125 * x @ Wq
        Ah = xhi; Al = xlo; Bh = wqh; Bl = wql; Ch = qh; Cl = ql; scale = 0.125f;
        aB = (int64_t)y * 131072;                    // y*128*1024
        bB = (int64_t)bx * 262144;                   // bx*256*1024
        cB = (int64_t)y * 131072 + bx * 256;
    } else if (y < 64) {            // k = ctx @ Wkv_k
        const int yy = y - 32;
        Ah = chi; Al = clo; Bh = wkh; Bl = wkl; Ch = kh; Cl = kl; scale = 1.f;
        aB = (int64_t)yy * 131072;
        bB = (int64_t)bx * 262144;
        cB = (int64_t)yy * 131072 + bx * 256;
    } else {                        // vt[b][h*64+vd][j] = Wkv_v^T @ ctx_b^T
        const int yy = y - 64, bt = yy >> 3, r = yy & 7;
        Ah = wkh + M20; Al = wkl + M20; Bh = chi; Bl = clo;
        Ch = vth; Cl = vtl; scale = 1.f;
        aB = (int64_t)r * 131072;
        bB = (int64_t)bt * M20 + (int64_t)bx * 262144;
        cB = (int64_t)bt * M20 + (int64_t)r * 131072 + bx * 256;
    }
    gemm_body<128, 256, 2, 4, 1024, true>(Ah, Al, aB, 1024, Bh, Bl, bB, 1024,
                                          nullptr, Ch, Cl, cB, 1024, scale, smem);
}

// ---------------------------------------------------------------- generic strided GEMM kernel
// Per-z offsets: (z>>4)*S1 + (z&15)*S2 elements.
template<int BM, int BN, int WGM, int WGN, int KDIM, bool SPLIT_OUT>
__global__ __launch_bounds__(WGM * WGN * 32)
void hmma_gemm(const bf16* __restrict__ Ahi, const bf16* __restrict__ Alo,
               int64_t aS1, int64_t aS2, int64_t lda,
               const bf16* __restrict__ Bhi, const bf16* __restrict__ Blo,
               int64_t bS1, int64_t bS2, int64_t ldb,
               float* __restrict__ Cf, bf16* __restrict__ Chi, bf16* __restrict__ Clo,
               int64_t cS1, int64_t cS2, int64_t ldc, float scale)
{
    extern __shared__ char smem[];
    const int z = blockIdx.z;
    const int64_t aB = (int64_t)(z >> 4) * aS1 + (int64_t)(z & 15) * aS2
                     + (int64_t)blockIdx.y * BM * lda;
    const int64_t bB = (int64_t)(z >> 4) * bS1 + (int64_t)(z & 15) * bS2
                     + (int64_t)blockIdx.x * BN * ldb;
    const int64_t cB = (int64_t)(z >> 4) * cS1 + (int64_t)(z & 15) * cS2
                     + (int64_t)blockIdx.y * BM * ldc + (int64_t)blockIdx.x * BN;
    gemm_body<BM, BN, WGM, WGN, KDIM, SPLIT_OUT>(Ahi, Alo, aB, lda, Bhi, Blo, bB, ldb,
                                                 Cf, Chi, Clo, cB, ldc, scale, smem);
}

// ---------------------------------------------------------------- softmax + talking heads + LN
__global__ __launch_bounds__(256) void softtalk_kernel(
    const float* __restrict__ Wt, const float* __restrict__ gamma, const float* __restrict__ beta)
{
    extern __shared__ float sm[];        // [0:256) Wt, [256:272) gamma, [288:304) beta, rows @512
    float* rows = sm + 512;              // 16 rows x 1028
    const int tid = threadIdx.x;
    sm[tid] = Wt[tid];
    if (tid < 16) { sm[256 + tid] = gamma[tid]; sm[288 + tid] = beta[tid]; }
    const int b = blockIdx.x >> 10, i = blockIdx.x & 1023;
    const size_t base = ((size_t)b * 16) << 20;
    const size_t irow = (size_t)i * 1024;
#pragma unroll
    for (int h = 0; h < 16; ++h)
        *(float4*)(rows + h * 1028 + tid * 4) =
            *(const float4*)(g_w + base + ((size_t)h << 20) + irow + tid * 4);
    __syncthreads();

    const int wid = tid >> 5, lane = tid & 31;
#pragma unroll
    for (int rr = wid; rr < 16; rr += 8) {
        float* r = rows + rr * 1028;
        float mx = -1e30f;
        for (int j = lane; j < 1024; j += 32) mx = fmaxf(mx, r[j]);
#pragma unroll
        for (int o = 16; o; o >>= 1) mx = fmaxf(mx, __shfl_xor_sync(~0u, mx, o));
        float s = 0.f;
        for (int j = lane; j < 1024; j += 32) { float e = __expf(r[j] - mx); r[j] = e; s += e; }
#pragma unroll
        for (int o = 16; o; o >>= 1) s += __shfl_xor_sync(~0u, s, o);
        const float inv = 1.f / s;
        for (int j = lane; j < 1024; j += 32) r[j] *= inv;
    }
    __syncthreads();

#pragma unroll
    for (int jj = 0; jj < 4; ++jj) {
        const int j = tid + jj * 256;
        float o[16];
#pragma unroll
        for (int g = 0; g < 16; ++g) o[g] = 0.f;
#pragma unroll
        for (int h = 0; h < 16; ++h) {
            const float v = rows[h * 1028 + j];
#pragma unroll
            for (int g = 0; g < 16; ++g) o[g] = fmaf(v, sm[h * 16 + g], o[g]);
        }
        float mu = 0.f;
#pragma unroll
        for (int g = 0; g < 16; ++g) mu += o[g];
        mu *= 0.0625f;
        float var = 0.f;
#pragma unroll
        for (int g = 0; g < 16; ++g) { const float dd = o[g] - mu; var = fmaf(dd, dd, var); }
        var *= 0.0625f;
        const float rstd = rsqrtf(var + 1e-5f);
#pragma unroll
        for (int g = 0; g < 16; ++g) {
            const float val = (o[g] - mu) * rstd * sm[256 + g] + sm[288 + g];
            unsigned short h16, l16;
            split2(val, h16, l16);
            const size_t oo = base + ((size_t)g << 20) + irow + j;
            g_whi[oo] = __ushort_as_bfloat16(h16);
            g_wlo[oo] = __ushort_as_bfloat16(l16);
        }
    }
}

// ---------------------------------------------------------------- launch
extern "C" void kernel_launch(void* const* d_in, const int* in_sizes, int n_in,
                              void* d_out, int out_size) {
    (void)in_sizes; (void)n_in; (void)out_size;
    const float* x   = (const float*)d_in[0];
    const float* ctx = (const float*)d_in[1];
    const float* Wq  = (const float*)d_in[2];
    const float* Wkv = (const float*)d_in[3];
    const float* Wt  = (const float*)d_in[4];
    const float* gm  = (const float*)d_in[5];
    const float* bt  = (const float*)d_in[6];
    float* out = (float*)d_out;

    bf16 *xhi, *xlo, *chi, *clo, *wqh, *wql, *wkh, *wkl;
    bf16 *qh, *ql, *kh, *kl, *vth, *vtl, *whi, *wlo;
    float* gw;
    cudaGetSymbolAddress((void**)&xhi, g_xhi);   cudaGetSymbolAddress((void**)&xlo, g_xlo);
    cudaGetSymbolAddress((void**)&chi, g_chi);   cudaGetSymbolAddress((void**)&clo, g_clo);
    cudaGetSymbolAddress((void**)&wqh, g_wqhi);  cudaGetSymbolAddress((void**)&wql, g_wqlo);
    cudaGetSymbolAddress((void**)&wkh, g_wkhi);  cudaGetSymbolAddress((void**)&wkl, g_wklo);
    cudaGetSymbolAddress((void**)&qh,  g_qhi);   cudaGetSymbolAddress((void**)&ql,  g_qlo);
    cudaGetSymbolAddress((void**)&kh,  g_khi);   cudaGetSymbolAddress((void**)&kl,  g_klo);
    cudaGetSymbolAddress((void**)&vth, g_vthi);  cudaGetSymbolAddress((void**)&vtl, g_vtlo);
    cudaGetSymbolAddress((void**)&whi, g_whi);   cudaGetSymbolAddress((void**)&wlo, g_wlo);
    cudaGetSymbolAddress((void**)&gw,  g_w);

    // proj: A 128x128B x2 + B 256x128B x2 = 96KB/stage -> 192KB
    // dots: (A+B both 128) 64KB single-ish (2 chunks worth allocated as before): 64KB
    // attnv: A 256x128B x2 + B 64x128B x2 = 80KB/stage -> 160KB
    constexpr int SMEM_PROJ = 2 * (2 * 16384 + 2 * 32768);   // 196608
    constexpr int SMEM_DOT  = (2 * 16384 + 2 * 16384);       // 65536 (K=64, single chunk)
    constexpr int SMEM_ATT  = 2 * (2 * 32768 + 2 * 8192);    // 163840
    constexpr int SST       = (512 + 16 * 1028) * 4;
    cudaFuncSetAttribute(proj3_kernel, cudaFuncAttributeMaxDynamicSharedMemorySize, SMEM_PROJ);
    cudaFuncSetAttribute(hmma_gemm<128, 128, 2, 4,   64, false>,
                         cudaFuncAttributeMaxDynamicSharedMemorySize, SMEM_DOT);
    cudaFuncSetAttribute(hmma_gemm<256,  64, 4, 2, 1024, false>,
                         cudaFuncAttributeMaxDynamicSharedMemorySize, SMEM_ATT);
    cudaFuncSetAttribute(softtalk_kernel, cudaFuncAttributeMaxDynamicSharedMemorySize, SST);

    const int64_t M20 = 1 << 20;

    split_kernel<<<4096, 256>>>(x, xhi, xlo);
    split_kernel<<<4096, 256>>>(ctx, chi, clo);
    tsplit_kernel<<<dim3(32, 32), dim3(32, 8)>>>(Wq,  wqh, wql, 1024, 1024);
    tsplit_kernel<<<dim3(64, 32), dim3(32, 8)>>>(Wkv, wkh, wkl, 1024, 2048);

    // merged q/k/vt projections: 384 CTAs (CTA tile 128x256)
    proj3_kernel<<<dim3(4, 96), 256, SMEM_PROJ>>>(
        xhi, xlo, chi, clo, wqh, wql, wkh, wkl, qh, ql, kh, kl, vth, vtl);

    // dots: per (b,h) 1024 x 1024 x 64 -> g_w fp32  (unchanged config)
    hmma_gemm<128, 128, 2, 4, 64, false><<<dim3(8, 8, 64), 256, SMEM_DOT>>>(
        qh, ql, M20, 64, 1024,  kh, kl, M20, 64, 1024,
        gw, nullptr, nullptr, 16 * M20, M20, 1024, 1.f);
    // softmax + talking + LN -> g_whi/g_wlo
    softtalk_kernel<<<4096, 256, SST>>>(Wt, gm, bt);
    // out = w @ v : per (b,h) 1024 x 64 x 1024 (CTA tile 256x64), scattered into d_out
    hmma_gemm<256, 64, 4, 2, 1024, false><<<dim3(1, 4, 64), 256, SMEM_ATT>>>(
        whi, wlo, 16 * M20, M20, 1024,  vth, vtl, M20, 65536, 1024,
        out, nullptr, nullptr, M20, 64, 1024, 1.f);
}

// round 15
// speedup vs baseline: 1.1781x; 1.0949x over previous
#include <cuda_runtime.h>
#include <cuda_fp16.h>
#include <cstdint>

using h16 = __half;

// CrossAttention B=4, N=M=1024, DIM=1024, H=16, d=vd=64.
// HMMA (mma.sync f16) with fp16x3 split precision (hi 11 bits + lo 11 bits),
// fp32 accumulators. R15 vs R14: bf16 -> fp16 splits everywhere;
// attnv uses single-plane fp16 w (2-pass: w*v_hi + w*v_lo), softtalk writes
// one fp16 plane (halves its write traffic and attnv's A read traffic).

// ---------------------------------------------------------------- scratch
__device__ __align__(16) h16 g_xhi[4194304], g_xlo[4194304];     // x split
__device__ __align__(16) h16 g_chi[4194304], g_clo[4194304];     // ctx split
__device__ __align__(16) h16 g_wqhi[1048576], g_wqlo[1048576];   // Wq^T  [out][in]
__device__ __align__(16) h16 g_wkhi[2097152], g_wklo[2097152];   // Wkv^T [out][in]
__device__ __align__(16) h16 g_qhi[4194304], g_qlo[4194304];     // q*0.125 [b*N+i][h*64+d]
__device__ __align__(16) h16 g_khi[4194304], g_klo[4194304];     // k       [b*M+j][h*64+d]
__device__ __align__(16) h16 g_vthi[4194304], g_vtlo[4194304];   // v^T [b][h*64+vd][j]
__device__ float g_w[67108864];                                  // scores fp32 [b,h,i,j]
__device__ __align__(16) h16 g_wh[67108864];                     // post-softtalk w (fp16, single plane)

// ---------------------------------------------------------------- helpers
__device__ __forceinline__ uint32_t smem_u32(const void* p) {
    uint32_t a;
    asm("{ .reg .u64 t; cvta.to.shared.u64 t, %1; cvt.u32.u64 %0, t; }" : "=r"(a) : "l"(p));
    return a;
}
__device__ __forceinline__ void split2(float v, unsigned short& h, unsigned short& l) {
    h16 hb = __float2half_rn(v);
    h = __half_as_ushort(hb);
    l = __half_as_ushort(__float2half_rn(v - __half2float(hb)));
}
#define SWZ(x) ((x) ^ (((x) >> 3) & 0x70))

__device__ __forceinline__ void cpa16(uint32_t dst, const void* src) {
    asm volatile("cp.async.cg.shared.global [%0], [%1], 16;" :: "r"(dst), "l"(src));
}
__device__ __forceinline__ void ldsm4(uint32_t r[4], uint32_t addr) {
    asm volatile("ldmatrix.sync.aligned.m8n8.x4.shared.b16 {%0,%1,%2,%3}, [%4];"
                 : "=r"(r[0]), "=r"(r[1]), "=r"(r[2]), "=r"(r[3]) : "r"(addr));
}
__device__ __forceinline__ void mma_f16(float c[4], const uint32_t a[4], const uint32_t b[2]) {
    asm volatile(
        "mma.sync.aligned.m16n8k16.row.col.f32.f16.f16.f32 "
        "{%0,%1,%2,%3}, {%4,%5,%6,%7}, {%8,%9}, {%0,%1,%2,%3};"
        : "+f"(c[0]), "+f"(c[1]), "+f"(c[2]), "+f"(c[3])
        : "r"(a[0]), "r"(a[1]), "r"(a[2]), "r"(a[3]), "r"(b[0]), "r"(b[1]));
}

// ---------------------------------------------------------------- prep kernels
__global__ __launch_bounds__(256) void split_kernel(const float* __restrict__ s,
                                                    h16* __restrict__ hi, h16* __restrict__ lo) {
    size_t i = (size_t)blockIdx.x * 256 + threadIdx.x;
    float4 v = ((const float4*)s)[i];
    unsigned short hh[4], ll[4];
    split2(v.x, hh[0], ll[0]); split2(v.y, hh[1], ll[1]);
    split2(v.z, hh[2], ll[2]); split2(v.w, hh[3], ll[3]);
    ((uint2*)hi)[i] = *(uint2*)hh;
    ((uint2*)lo)[i] = *(uint2*)ll;
}

__global__ void tsplit_kernel(const float* __restrict__ s, h16* __restrict__ hi,
                              h16* __restrict__ lo, int R, int C) {
    __shared__ float t[32][33];
    const int c0 = blockIdx.x * 32, r0 = blockIdx.y * 32;
    const int tx = threadIdx.x, ty = threadIdx.y;
#pragma unroll
    for (int k = 0; k < 4; ++k)
        t[ty + 8 * k][tx] = s[(size_t)(r0 + ty + 8 * k) * C + c0 + tx];
    __syncthreads();
#pragma unroll
    for (int k = 0; k < 4; ++k) {
        unsigned short h, l;
        split2(t[tx][ty + 8 * k], h, l);
        const size_t o = (size_t)(c0 + ty + 8 * k) * R + r0 + tx;
        hi[o] = __ushort_as_half(h);
        lo[o] = __ushort_as_half(l);
    }
}

// ---------------------------------------------------------------- GEMM body
// C[BM x BN] = sum_k A[m][k]*B[n][k]  (K-major fp16 planes).
// A_SINGLE=false: A hi/lo, 3 passes (hi*hi + hi*lo + lo*hi).
// A_SINGLE=true : A single plane, 2 passes (a*b_hi + a*b_lo).
// K-chunk 64 (128B rows, SW128), 2-stage, wait(1)/wait(0), two syncs per chunk.
template<int BM, int BN, int WGM, int WGN, int KDIM, bool SPLIT_OUT, bool A_SINGLE>
__device__ __forceinline__ void gemm_body(
    const h16* __restrict__ Ahi, const h16* __restrict__ Alo, int64_t aB, int64_t lda,
    const h16* __restrict__ Bhi, const h16* __restrict__ Blo, int64_t bB, int64_t ldb,
    float* __restrict__ Cf, h16* __restrict__ Chi, h16* __restrict__ Clo,
    int64_t cB, int64_t ldc, float scale, char* smem)
{
    constexpr int NT    = WGM * WGN * 32;
    constexpr int NC    = KDIM / 64;
    constexpr int APL   = A_SINGLE ? 1 : 2;     // A planes
    constexpr int ASTG  = BM * 128;             // bytes per A plane per stage
    constexpr int BSTG  = BN * 128;
    constexpr int STAGE = APL * ASTG + 2 * BSTG;
    constexpr int WN    = BN / WGN;             // warp n-extent
    constexpr int NFRAG = WN / 8;
    static_assert(BM / WGM == 64, "warp m-extent must be 64");

    const uint32_t sb = smem_u32(smem);
    const int tid = threadIdx.x, lane = tid & 31, wid = tid >> 5;
    const int wm = wid / WGN, wn = wid % WGN;

    float cf[4][NFRAG][4];
#pragma unroll
    for (int mf = 0; mf < 4; ++mf)
#pragma unroll
        for (int nf = 0; nf < NFRAG; ++nf)
#pragma unroll
            for (int q = 0; q < 4; ++q) cf[mf][nf][q] = 0.f;

    auto issue = [&](int c) {
        const uint32_t so = sb + (c & 1) * STAGE;
        const h16* ah = Ahi + aB + c * 64;
        const h16* al = A_SINGLE ? nullptr : (Alo + aB + c * 64);
#pragma unroll
        for (int s = tid; s < BM * 8; s += NT) {            // A: BM rows x 8 segs(16B)
            const int r = s >> 3, g = s & 7;
            const uint32_t sw = SWZ(r * 128 + g * 16);
            const int64_t go = (int64_t)r * lda + g * 8;
            cpa16(so + sw, ah + go);
            if constexpr (!A_SINGLE) cpa16(so + ASTG + sw, al + go);
        }
        const h16* bh = Bhi + bB + c * 64;
        const h16* bl = Blo + bB + c * 64;
#pragma unroll
        for (int s = tid; s < BN * 8; s += NT) {            // B: BN rows x 8 segs
            const int r = s >> 3, g = s & 7;
            const uint32_t sw = SWZ(r * 128 + g * 16);
            const int64_t go = (int64_t)r * ldb + g * 8;
            cpa16(so + APL * ASTG + sw, bh + go);
            cpa16(so + APL * ASTG + BSTG + sw, bl + go);
        }
        asm volatile("cp.async.commit_group;" ::: "memory");
    };

    const int l8 = lane & 7, sub = lane >> 3;
    const int arow = wm * 64 + l8 + (sub & 1) * 8;          // + mf*16
    const int asegsel = sub >> 1;
    const int brow = wn * WN + l8 + (sub >> 1) * 8;         // + nb*8
    const int bsegsel = sub & 1;

    auto compute = [&](int c) {
        const uint32_t sA  = sb + (c & 1) * STAGE;
        const uint32_t sBh = sA + APL * ASTG;
#pragma unroll
        for (int kk = 0; kk < 4; ++kk) {
            uint32_t af[APL][4][4];
#pragma unroll
            for (int mf = 0; mf < 4; ++mf) {
                const uint32_t ad = sA + SWZ((arow + mf * 16) * 128 + (kk * 2 + asegsel) * 16);
                ldsm4(af[0][mf], ad);
                if constexpr (!A_SINGLE) ldsm4(af[1][mf], ad + ASTG);
            }
            uint32_t bfr[2][NFRAG][2];
#pragma unroll
            for (int nb = 0; nb < NFRAG; nb += 2) {
                const uint32_t bd = SWZ((brow + nb * 8) * 128 + (kk * 2 + bsegsel) * 16);
                uint32_t t[4];
                ldsm4(t, sBh + bd);
                bfr[0][nb][0] = t[0]; bfr[0][nb][1] = t[1];
                bfr[0][nb + 1][0] = t[2]; bfr[0][nb + 1][1] = t[3];
                ldsm4(t, sBh + BSTG + bd);
                bfr[1][nb][0] = t[0]; bfr[1][nb][1] = t[1];
                bfr[1][nb + 1][0] = t[2]; bfr[1][nb + 1][1] = t[3];
            }
#pragma unroll
            for (int mf = 0; mf < 4; ++mf)
#pragma unroll
                for (int nf = 0; nf < NFRAG; ++nf) {
                    if constexpr (A_SINGLE) {
                        mma_f16(cf[mf][nf], af[0][mf], bfr[0][nf]);   // a*b_hi
                        mma_f16(cf[mf][nf], af[0][mf], bfr[1][nf]);   // a*b_lo
                    } else {
                        mma_f16(cf[mf][nf], af[0][mf], bfr[0][nf]);   // hi*hi
                        mma_f16(cf[mf][nf], af[0][mf], bfr[1][nf]);   // hi*lo
                        mma_f16(cf[mf][nf], af[1][mf], bfr[0][nf]);   // lo*hi
                    }
                }
        }
    };

    issue(0);
    if (NC > 1) issue(1);
    for (int c = 0; c < NC; ++c) {
        if (c + 1 < NC) asm volatile("cp.async.wait_group 1;" ::: "memory");
        else            asm volatile("cp.async.wait_group 0;" ::: "memory");
        __syncthreads();
        compute(c);
        __syncthreads();
        if (c + 2 < NC) issue(c + 2);
    }

    const int crow0 = wm * 64 + lane / 4;
    const int ccol0 = wn * WN + (lane % 4) * 2;
#pragma unroll
    for (int mf = 0; mf < 4; ++mf)
#pragma unroll
        for (int nf = 0; nf < NFRAG; ++nf) {
            const int64_t o0 = cB + (int64_t)(crow0 + mf * 16) * ldc + ccol0 + nf * 8;
            const int64_t o1 = o0 + 8 * ldc;
            if constexpr (SPLIT_OUT) {
                unsigned short h0, l0, h1, l1;
                split2(cf[mf][nf][0] * scale, h0, l0);
                split2(cf[mf][nf][1] * scale, h1, l1);
                *(uint32_t*)&Chi[o0] = (uint32_t)h0 | ((uint32_t)h1 << 16);
                *(uint32_t*)&Clo[o0] = (uint32_t)l0 | ((uint32_t)l1 << 16);
                split2(cf[mf][nf][2] * scale, h0, l0);
                split2(cf[mf][nf][3] * scale, h1, l1);
                *(uint32_t*)&Chi[o1] = (uint32_t)h0 | ((uint32_t)h1 << 16);
                *(uint32_t*)&Clo[o1] = (uint32_t)l0 | ((uint32_t)l1 << 16);
            } else {
                *(float2*)&Cf[o0] = make_float2(cf[mf][nf][0], cf[mf][nf][1]);
                *(float2*)&Cf[o1] = make_float2(cf[mf][nf][2], cf[mf][nf][3]);
            }
        }
}

// ---------------------------------------------------------------- merged q/k/vt projections
// CTA tile 128x256, warp 64x64. grid (4, 96): y in [0,32) q, [32,64) k, [64,96) vt.
__global__ __launch_bounds__(256)
void proj3_kernel(const h16* __restrict__ xhi, const h16* __restrict__ xlo,
                  const h16* __restrict__ chi, const h16* __restrict__ clo,
                  const h16* __restrict__ wqh, const h16* __restrict__ wql,
                  const h16* __restrict__ wkh, const h16* __restrict__ wkl,
                  h16* __restrict__ qh, h16* __restrict__ ql,
                  h16* __restrict__ kh, h16* __restrict__ kl,
                  h16* __restrict__ vth, h16* __restrict__ vtl)
{
    extern __shared__ char smem[];
    const int64_t M20 = 1 << 20;
    const int y = blockIdx.y, bx = blockIdx.x;
    const h16 *Ah, *Al, *Bh, *Bl;
    h16 *Ch, *Cl;
    int64_t aB, bB, cB;
    float scale;
    if (y < 32) {                   // q = 0.125 * x @ Wq
        Ah = xhi; Al = xlo; Bh = wqh; Bl = wql; Ch = qh; Cl = ql; scale = 0.125f;
        aB = (int64_t)y * 131072;                    // y*128*1024
        bB = (int64_t)bx * 262144;                   // bx*256*1024
        cB = (int64_t)y * 131072 + bx * 256;
    } else if (y < 64) {            // k = ctx @ Wkv_k
        const int yy = y - 32;
        Ah = chi; Al = clo; Bh = wkh; Bl = wkl; Ch = kh; Cl = kl; scale = 1.f;
        aB = (int64_t)yy * 131072;
        bB = (int64_t)bx * 262144;
        cB = (int64_t)yy * 131072 + bx * 256;
    } else {                        // vt[b][h*64+vd][j] = Wkv_v^T @ ctx_b^T
        const int yy = y - 64, bt = yy >> 3, r = yy & 7;
        Ah = wkh + M20; Al = wkl + M20; Bh = chi; Bl = clo;
        Ch = vth; Cl = vtl; scale = 1.f;
        aB = (int64_t)r * 131072;
        bB = (int64_t)bt * M20 + (int64_t)bx * 262144;
        cB = (int64_t)bt * M20 + (int64_t)r * 131072 + bx * 256;
    }
    gemm_body<128, 256, 2, 4, 1024, true, false>(Ah, Al, aB, 1024, Bh, Bl, bB, 1024,
                                                 nullptr, Ch, Cl, cB, 1024, scale, smem);
}

// ---------------------------------------------------------------- generic strided GEMM kernel
// Per-z offsets: (z>>4)*S1 + (z&15)*S2 elements.
template<int BM, int BN, int WGM, int WGN, int KDIM, bool SPLIT_OUT, bool A_SINGLE>
__global__ __launch_bounds__(WGM * WGN * 32)
void hmma_gemm(const h16* __restrict__ Ahi, const h16* __restrict__ Alo,
               int64_t aS1, int64_t aS2, int64_t lda,
               const h16* __restrict__ Bhi, const h16* __restrict__ Blo,
               int64_t bS1, int64_t bS2, int64_t ldb,
               float* __restrict__ Cf, h16* __restrict__ Chi, h16* __restrict__ Clo,
               int64_t cS1, int64_t cS2, int64_t ldc, float scale)
{
    extern __shared__ char smem[];
    const int z = blockIdx.z;
    const int64_t aB = (int64_t)(z >> 4) * aS1 + (int64_t)(z & 15) * aS2
                     + (int64_t)blockIdx.y * BM * lda;
    const int64_t bB = (int64_t)(z >> 4) * bS1 + (int64_t)(z & 15) * bS2
                     + (int64_t)blockIdx.x * BN * ldb;
    const int64_t cB = (int64_t)(z >> 4) * cS1 + (int64_t)(z & 15) * cS2
                     + (int64_t)blockIdx.y * BM * ldc + (int64_t)blockIdx.x * BN;
    gemm_body<BM, BN, WGM, WGN, KDIM, SPLIT_OUT, A_SINGLE>(
        Ahi, Alo, aB, lda, Bhi, Blo, bB, ldb, Cf, Chi, Clo, cB, ldc, scale, smem);
}

// ---------------------------------------------------------------- softmax + talking heads + LN
// One block per (b,i): 16 heads x 1024 j. Reads g_w fp32, writes g_wh fp16 (single plane).
__global__ __launch_bounds__(256) void softtalk_kernel(
    const float* __restrict__ Wt, const float* __restrict__ gamma, const float* __restrict__ beta)
{
    extern __shared__ float sm[];        // [0:256) Wt, [256:272) gamma, [288:304) beta, rows @512
    float* rows = sm + 512;              // 16 rows x 1028
    const int tid = threadIdx.x;
    sm[tid] = Wt[tid];
    if (tid < 16) { sm[256 + tid] = gamma[tid]; sm[288 + tid] = beta[tid]; }
    const int b = blockIdx.x >> 10, i = blockIdx.x & 1023;
    const size_t base = ((size_t)b * 16) << 20;
    const size_t irow = (size_t)i * 1024;
#pragma unroll
    for (int h = 0; h < 16; ++h)
        *(float4*)(rows + h * 1028 + tid * 4) =
            *(const float4*)(g_w + base + ((size_t)h << 20) + irow + tid * 4);
    __syncthreads();

    const int wid = tid >> 5, lane = tid & 31;
#pragma unroll
    for (int rr = wid; rr < 16; rr += 8) {
        float* r = rows + rr * 1028;
        float mx = -1e30f;
        for (int j = lane; j < 1024; j += 32) mx = fmaxf(mx, r[j]);
#pragma unroll
        for (int o = 16; o; o >>= 1) mx = fmaxf(mx, __shfl_xor_sync(~0u, mx, o));
        float s = 0.f;
        for (int j = lane; j < 1024; j += 32) { float e = __expf(r[j] - mx); r[j] = e; s += e; }
#pragma unroll
        for (int o = 16; o; o >>= 1) s += __shfl_xor_sync(~0u, s, o);
        const float inv = 1.f / s;
        for (int j = lane; j < 1024; j += 32) r[j] *= inv;
    }
    __syncthreads();

#pragma unroll
    for (int jj = 0; jj < 4; ++jj) {
        const int j = tid + jj * 256;
        float o[16];
#pragma unroll
        for (int g = 0; g < 16; ++g) o[g] = 0.f;
#pragma unroll
        for (int h = 0; h < 16; ++h) {
            const float v = rows[h * 1028 + j];
#pragma unroll
            for (int g = 0; g < 16; ++g) o[g] = fmaf(v, sm[h * 16 + g], o[g]);
        }
        float mu = 0.f;
#pragma unroll
        for (int g = 0; g < 16; ++g) mu += o[g];
        mu *= 0.0625f;
        float var = 0.f;
#pragma unroll
        for (int g = 0; g < 16; ++g) { const float dd = o[g] - mu; var = fmaf(dd, dd, var); }
        var *= 0.0625f;
        const float rstd = rsqrtf(var + 1e-5f);
#pragma unroll
        for (int g = 0; g < 16; ++g) {
            const float val = (o[g] - mu) * rstd * sm[256 + g] + sm[288 + g];
            g_wh[base + ((size_t)g << 20) + irow + j] = __float2half_rn(val);
        }
    }
}

// ---------------------------------------------------------------- launch
extern "C" void kernel_launch(void* const* d_in, const int* in_sizes, int n_in,
                              void* d_out, int out_size) {
    (void)in_sizes; (void)n_in; (void)out_size;
    const float* x   = (const float*)d_in[0];
    const float* ctx = (const float*)d_in[1];
    const float* Wq  = (const float*)d_in[2];
    const float* Wkv = (const float*)d_in[3];
    const float* Wt  = (const float*)d_in[4];
    const float* gm  = (const float*)d_in[5];
    const float* bt  = (const float*)d_in[6];
    float* out = (float*)d_out;

    h16 *xhi, *xlo, *chi, *clo, *wqh, *wql, *wkh, *wkl;
    h16 *qh, *ql, *kh, *kl, *vth, *vtl, *wh;
    float* gw;
    cudaGetSymbolAddress((void**)&xhi, g_xhi);   cudaGetSymbolAddress((void**)&xlo, g_xlo);
    cudaGetSymbolAddress((void**)&chi, g_chi);   cudaGetSymbolAddress((void**)&clo, g_clo);
    cudaGetSymbolAddress((void**)&wqh, g_wqhi);  cudaGetSymbolAddress((void**)&wql, g_wqlo);
    cudaGetSymbolAddress((void**)&wkh, g_wkhi);  cudaGetSymbolAddress((void**)&wkl, g_wklo);
    cudaGetSymbolAddress((void**)&qh,  g_qhi);   cudaGetSymbolAddress((void**)&ql,  g_qlo);
    cudaGetSymbolAddress((void**)&kh,  g_khi);   cudaGetSymbolAddress((void**)&kl,  g_klo);
    cudaGetSymbolAddress((void**)&vth, g_vthi);  cudaGetSymbolAddress((void**)&vtl, g_vtlo);
    cudaGetSymbolAddress((void**)&wh,  g_wh);
    cudaGetSymbolAddress((void**)&gw,  g_w);

    // proj: (2 A planes 16KB + 2 B planes 32KB) x2 stages = 192KB
    // dots: single chunk, 64KB
    // attnv: A_SINGLE: (1 A plane 32KB + 2 B planes 8KB) x2 = 96KB
    constexpr int SMEM_PROJ = 2 * (2 * 16384 + 2 * 32768);   // 196608
    constexpr int SMEM_DOT  = (2 * 16384 + 2 * 16384);       // 65536
    constexpr int SMEM_ATT  = 2 * (1 * 32768 + 2 * 8192);    // 98304
    constexpr int SST       = (512 + 16 * 1028) * 4;
    cudaFuncSetAttribute(proj3_kernel, cudaFuncAttributeMaxDynamicSharedMemorySize, SMEM_PROJ);
    cudaFuncSetAttribute(hmma_gemm<128, 128, 2, 4,   64, false, false>,
                         cudaFuncAttributeMaxDynamicSharedMemorySize, SMEM_DOT);
    cudaFuncSetAttribute(hmma_gemm<256,  64, 4, 2, 1024, false, true>,
                         cudaFuncAttributeMaxDynamicSharedMemorySize, SMEM_ATT);
    cudaFuncSetAttribute(softtalk_kernel, cudaFuncAttributeMaxDynamicSharedMemorySize, SST);

    const int64_t M20 = 1 << 20;

    split_kernel<<<4096, 256>>>(x, xhi, xlo);
    split_kernel<<<4096, 256>>>(ctx, chi, clo);
    tsplit_kernel<<<dim3(32, 32), dim3(32, 8)>>>(Wq,  wqh, wql, 1024, 1024);
    tsplit_kernel<<<dim3(64, 32), dim3(32, 8)>>>(Wkv, wkh, wkl, 1024, 2048);

    // merged q/k/vt projections: 384 CTAs (CTA tile 128x256)
    proj3_kernel<<<dim3(4, 96), 256, SMEM_PROJ>>>(
        xhi, xlo, chi, clo, wqh, wql, wkh, wkl, qh, ql, kh, kl, vth, vtl);

    // dots: per (b,h) 1024 x 1024 x 64 -> g_w fp32
    hmma_gemm<128, 128, 2, 4, 64, false, false><<<dim3(8, 8, 64), 256, SMEM_DOT>>>(
        qh, ql, M20, 64, 1024,  kh, kl, M20, 64, 1024,
        gw, nullptr, nullptr, 16 * M20, M20, 1024, 1.f);
    // softmax + talking + LN -> g_wh (fp16 single plane)
    softtalk_kernel<<<4096, 256, SST>>>(Wt, gm, bt);
    // out = w @ v : per (b,h) 1024 x 64 x 1024 (CTA 256x64), A single-plane fp16 w
    hmma_gemm<256, 64, 4, 2, 1024, false, true><<<dim3(1, 4, 64), 256, SMEM_ATT>>>(
        wh, nullptr, 16 * M20, M20, 1024,  vth, vtl, M20, 65536, 1024,
        out, nullptr, nullptr, M20, 64, 1024, 1.f);
}

// round 16
// speedup vs baseline: 1.2099x; 1.0269x over previous
#include <cuda_runtime.h>
#include <cuda_fp16.h>
#include <cstdint>

using h16 = __half;

// CrossAttention B=4, N=M=1024, DIM=1024, H=16, d=vd=64.
// HMMA (mma.sync f16) with fp16x3 split precision, fp32 accumulators.
// R16 vs R15: logits plane g_w fp32 -> g_wl fp16 (halves dots write + softtalk
// read traffic). GEMM template gains OUTMODE: 0=f32, 1=split hi/lo, 2=f16.

// ---------------------------------------------------------------- scratch
__device__ __align__(16) h16 g_xhi[4194304], g_xlo[4194304];     // x split
__device__ __align__(16) h16 g_chi[4194304], g_clo[4194304];     // ctx split
__device__ __align__(16) h16 g_wqhi[1048576], g_wqlo[1048576];   // Wq^T  [out][in]
__device__ __align__(16) h16 g_wkhi[2097152], g_wklo[2097152];   // Wkv^T [out][in]
__device__ __align__(16) h16 g_qhi[4194304], g_qlo[4194304];     // q*0.125 [b*N+i][h*64+d]
__device__ __align__(16) h16 g_khi[4194304], g_klo[4194304];     // k       [b*M+j][h*64+d]
__device__ __align__(16) h16 g_vthi[4194304], g_vtlo[4194304];   // v^T [b][h*64+vd][j]
__device__ __align__(16) h16 g_wl[67108864];                     // logits fp16 [b,h,i,j]
__device__ __align__(16) h16 g_wh[67108864];                     // post-softtalk w fp16

// ---------------------------------------------------------------- helpers
__device__ __forceinline__ uint32_t smem_u32(const void* p) {
    uint32_t a;
    asm("{ .reg .u64 t; cvta.to.shared.u64 t, %1; cvt.u32.u64 %0, t; }" : "=r"(a) : "l"(p));
    return a;
}
__device__ __forceinline__ void split2(float v, unsigned short& h, unsigned short& l) {
    h16 hb = __float2half_rn(v);
    h = __half_as_ushort(hb);
    l = __half_as_ushort(__float2half_rn(v - __half2float(hb)));
}
#define SWZ(x) ((x) ^ (((x) >> 3) & 0x70))

__device__ __forceinline__ void cpa16(uint32_t dst, const void* src) {
    asm volatile("cp.async.cg.shared.global [%0], [%1], 16;" :: "r"(dst), "l"(src));
}
__device__ __forceinline__ void ldsm4(uint32_t r[4], uint32_t addr) {
    asm volatile("ldmatrix.sync.aligned.m8n8.x4.shared.b16 {%0,%1,%2,%3}, [%4];"
                 : "=r"(r[0]), "=r"(r[1]), "=r"(r[2]), "=r"(r[3]) : "r"(addr));
}
__device__ __forceinline__ void mma_f16(float c[4], const uint32_t a[4], const uint32_t b[2]) {
    asm volatile(
        "mma.sync.aligned.m16n8k16.row.col.f32.f16.f16.f32 "
        "{%0,%1,%2,%3}, {%4,%5,%6,%7}, {%8,%9}, {%0,%1,%2,%3};"
        : "+f"(c[0]), "+f"(c[1]), "+f"(c[2]), "+f"(c[3])
        : "r"(a[0]), "r"(a[1]), "r"(a[2]), "r"(a[3]), "r"(b[0]), "r"(b[1]));
}
__device__ __forceinline__ uint32_t pack_h2(float a, float b) {
    return (uint32_t)__half_as_ushort(__float2half_rn(a))
         | ((uint32_t)__half_as_ushort(__float2half_rn(b)) << 16);
}

// ---------------------------------------------------------------- prep kernels
__global__ __launch_bounds__(256) void split_kernel(const float* __restrict__ s,
                                                    h16* __restrict__ hi, h16* __restrict__ lo) {
    size_t i = (size_t)blockIdx.x * 256 + threadIdx.x;
    float4 v = ((const float4*)s)[i];
    unsigned short hh[4], ll[4];
    split2(v.x, hh[0], ll[0]); split2(v.y, hh[1], ll[1]);
    split2(v.z, hh[2], ll[2]); split2(v.w, hh[3], ll[3]);
    ((uint2*)hi)[i] = *(uint2*)hh;
    ((uint2*)lo)[i] = *(uint2*)ll;
}

__global__ void tsplit_kernel(const float* __restrict__ s, h16* __restrict__ hi,
                              h16* __restrict__ lo, int R, int C) {
    __shared__ float t[32][33];
    const int c0 = blockIdx.x * 32, r0 = blockIdx.y * 32;
    const int tx = threadIdx.x, ty = threadIdx.y;
#pragma unroll
    for (int k = 0; k < 4; ++k)
        t[ty + 8 * k][tx] = s[(size_t)(r0 + ty + 8 * k) * C + c0 + tx];
    __syncthreads();
#pragma unroll
    for (int k = 0; k < 4; ++k) {
        unsigned short h, l;
        split2(t[tx][ty + 8 * k], h, l);
        const size_t o = (size_t)(c0 + ty + 8 * k) * R + r0 + tx;
        hi[o] = __ushort_as_half(h);
        lo[o] = __ushort_as_half(l);
    }
}

// ---------------------------------------------------------------- GEMM body
// C[BM x BN] = sum_k A[m][k]*B[n][k]  (K-major fp16 planes).
// A_SINGLE=false: A hi/lo, 3 passes. A_SINGLE=true: A single plane, 2 passes.
// OUTMODE: 0 = fp32 C, 1 = split hi/lo fp16 C, 2 = single fp16 C.
// K-chunk 64 (128B rows, SW128), 2-stage, wait(1)/wait(0), two syncs per chunk.
template<int BM, int BN, int WGM, int WGN, int KDIM, int OUTMODE, bool A_SINGLE>
__device__ __forceinline__ void gemm_body(
    const h16* __restrict__ Ahi, const h16* __restrict__ Alo, int64_t aB, int64_t lda,
    const h16* __restrict__ Bhi, const h16* __restrict__ Blo, int64_t bB, int64_t ldb,
    float* __restrict__ Cf, h16* __restrict__ Chi, h16* __restrict__ Clo,
    int64_t cB, int64_t ldc, float scale, char* smem)
{
    constexpr int NT    = WGM * WGN * 32;
    constexpr int NC    = KDIM / 64;
    constexpr int APL   = A_SINGLE ? 1 : 2;     // A planes
    constexpr int ASTG  = BM * 128;             // bytes per A plane per stage
    constexpr int BSTG  = BN * 128;
    constexpr int STAGE = APL * ASTG + 2 * BSTG;
    constexpr int WN    = BN / WGN;             // warp n-extent
    constexpr int NFRAG = WN / 8;
    static_assert(BM / WGM == 64, "warp m-extent must be 64");

    const uint32_t sb = smem_u32(smem);
    const int tid = threadIdx.x, lane = tid & 31, wid = tid >> 5;
    const int wm = wid / WGN, wn = wid % WGN;

    float cf[4][NFRAG][4];
#pragma unroll
    for (int mf = 0; mf < 4; ++mf)
#pragma unroll
        for (int nf = 0; nf < NFRAG; ++nf)
#pragma unroll
            for (int q = 0; q < 4; ++q) cf[mf][nf][q] = 0.f;

    auto issue = [&](int c) {
        const uint32_t so = sb + (c & 1) * STAGE;
        const h16* ah = Ahi + aB + c * 64;
        const h16* al = A_SINGLE ? nullptr : (Alo + aB + c * 64);
#pragma unroll
        for (int s = tid; s < BM * 8; s += NT) {            // A: BM rows x 8 segs(16B)
            const int r = s >> 3, g = s & 7;
            const uint32_t sw = SWZ(r * 128 + g * 16);
            const int64_t go = (int64_t)r * lda + g * 8;
            cpa16(so + sw, ah + go);
            if constexpr (!A_SINGLE) cpa16(so + ASTG + sw, al + go);
        }
        const h16* bh = Bhi + bB + c * 64;
        const h16* bl = Blo + bB + c * 64;
#pragma unroll
        for (int s = tid; s < BN * 8; s += NT) {            // B: BN rows x 8 segs
            const int r = s >> 3, g = s & 7;
            const uint32_t sw = SWZ(r * 128 + g * 16);
            const int64_t go = (int64_t)r * ldb + g * 8;
            cpa16(so + APL * ASTG + sw, bh + go);
            cpa16(so + APL * ASTG + BSTG + sw, bl + go);
        }
        asm volatile("cp.async.commit_group;" ::: "memory");
    };

    const int l8 = lane & 7, sub = lane >> 3;
    const int arow = wm * 64 + l8 + (sub & 1) * 8;          // + mf*16
    const int asegsel = sub >> 1;
    const int brow = wn * WN + l8 + (sub >> 1) * 8;         // + nb*8
    const int bsegsel = sub & 1;

    auto compute = [&](int c) {
        const uint32_t sA  = sb + (c & 1) * STAGE;
        const uint32_t sBh = sA + APL * ASTG;
#pragma unroll
        for (int kk = 0; kk < 4; ++kk) {
            uint32_t af[APL][4][4];
#pragma unroll
            for (int mf = 0; mf < 4; ++mf) {
                const uint32_t ad = sA + SWZ((arow + mf * 16) * 128 + (kk * 2 + asegsel) * 16);
                ldsm4(af[0][mf], ad);
                if constexpr (!A_SINGLE) ldsm4(af[1][mf], ad + ASTG);
            }
            uint32_t bfr[2][NFRAG][2];
#pragma unroll
            for (int nb = 0; nb < NFRAG; nb += 2) {
                const uint32_t bd = SWZ((brow + nb * 8) * 128 + (kk * 2 + bsegsel) * 16);
                uint32_t t[4];
                ldsm4(t, sBh + bd);
                bfr[0][nb][0] = t[0]; bfr[0][nb][1] = t[1];
                bfr[0][nb + 1][0] = t[2]; bfr[0][nb + 1][1] = t[3];
                ldsm4(t, sBh + BSTG + bd);
                bfr[1][nb][0] = t[0]; bfr[1][nb][1] = t[1];
                bfr[1][nb + 1][0] = t[2]; bfr[1][nb + 1][1] = t[3];
            }
#pragma unroll
            for (int mf = 0; mf < 4; ++mf)
#pragma unroll
                for (int nf = 0; nf < NFRAG; ++nf) {
                    if constexpr (A_SINGLE) {
                        mma_f16(cf[mf][nf], af[0][mf], bfr[0][nf]);   // a*b_hi
                        mma_f16(cf[mf][nf], af[0][mf], bfr[1][nf]);   // a*b_lo
                    } else {
                        mma_f16(cf[mf][nf], af[0][mf], bfr[0][nf]);   // hi*hi
                        mma_f16(cf[mf][nf], af[0][mf], bfr[1][nf]);   // hi*lo
                        mma_f16(cf[mf][nf], af[1][mf], bfr[0][nf]);   // lo*hi
                    }
                }
        }
    };

    issue(0);
    if (NC > 1) issue(1);
    for (int c = 0; c < NC; ++c) {
        if (c + 1 < NC) asm volatile("cp.async.wait_group 1;" ::: "memory");
        else            asm volatile("cp.async.wait_group 0;" ::: "memory");
        __syncthreads();
        compute(c);
        __syncthreads();
        if (c + 2 < NC) issue(c + 2);
    }

    const int crow0 = wm * 64 + lane / 4;
    const int ccol0 = wn * WN + (lane % 4) * 2;
#pragma unroll
    for (int mf = 0; mf < 4; ++mf)
#pragma unroll
        for (int nf = 0; nf < NFRAG; ++nf) {
            const int64_t o0 = cB + (int64_t)(crow0 + mf * 16) * ldc + ccol0 + nf * 8;
            const int64_t o1 = o0 + 8 * ldc;
            if constexpr (OUTMODE == 1) {
                unsigned short h0, l0, h1, l1;
                split2(cf[mf][nf][0] * scale, h0, l0);
                split2(cf[mf][nf][1] * scale, h1, l1);
                *(uint32_t*)&Chi[o0] = (uint32_t)h0 | ((uint32_t)h1 << 16);
                *(uint32_t*)&Clo[o0] = (uint32_t)l0 | ((uint32_t)l1 << 16);
                split2(cf[mf][nf][2] * scale, h0, l0);
                split2(cf[mf][nf][3] * scale, h1, l1);
                *(uint32_t*)&Chi[o1] = (uint32_t)h0 | ((uint32_t)h1 << 16);
                *(uint32_t*)&Clo[o1] = (uint32_t)l0 | ((uint32_t)l1 << 16);
            } else if constexpr (OUTMODE == 2) {
                *(uint32_t*)&Chi[o0] = pack_h2(cf[mf][nf][0] * scale, cf[mf][nf][1] * scale);
                *(uint32_t*)&Chi[o1] = pack_h2(cf[mf][nf][2] * scale, cf[mf][nf][3] * scale);
            } else {
                *(float2*)&Cf[o0] = make_float2(cf[mf][nf][0], cf[mf][nf][1]);
                *(float2*)&Cf[o1] = make_float2(cf[mf][nf][2], cf[mf][nf][3]);
            }
        }
}

// ---------------------------------------------------------------- merged q/k/vt projections
// CTA tile 128x256, warp 64x64. grid (4, 96): y in [0,32) q, [32,64) k, [64,96) vt.
__global__ __launch_bounds__(256)
void proj3_kernel(const h16* __restrict__ xhi, const h16* __restrict__ xlo,
                  const h16* __restrict__ chi, const h16* __restrict__ clo,
                  const h16* __restrict__ wqh, const h16* __restrict__ wql,
                  const h16* __restrict__ wkh, const h16* __restrict__ wkl,
                  h16* __restrict__ qh, h16* __restrict__ ql,
                  h16* __restrict__ kh, h16* __restrict__ kl,
                  h16* __restrict__ vth, h16* __restrict__ vtl)
{
    extern __shared__ char smem[];
    const int64_t M20 = 1 << 20;
    const int y = blockIdx.y, bx = blockIdx.x;
    const h16 *Ah, *Al, *Bh, *Bl;
    h16 *Ch, *Cl;
    int64_t aB, bB, cB;
    float scale;
    if (y < 32) {                   // q = 0.125 * x @ Wq
        Ah = xhi; Al = xlo; Bh = wqh; Bl = wql; Ch = qh; Cl = ql; scale = 0.125f;
        aB = (int64_t)y * 131072;                    // y*128*1024
        bB = (int64_t)bx * 262144;                   // bx*256*1024
        cB = (int64_t)y * 131072 + bx * 256;
    } else if (y < 64) {            // k = ctx @ Wkv_k
        const int yy = y - 32;
        Ah = chi; Al = clo; Bh = wkh; Bl = wkl; Ch = kh; Cl = kl; scale = 1.f;
        aB = (int64_t)yy * 131072;
        bB = (int64_t)bx * 262144;
        cB = (int64_t)yy * 131072 + bx * 256;
    } else {                        // vt[b][h*64+vd][j] = Wkv_v^T @ ctx_b^T
        const int yy = y - 64, bt = yy >> 3, r = yy & 7;
        Ah = wkh + M20; Al = wkl + M20; Bh = chi; Bl = clo;
        Ch = vth; Cl = vtl; scale = 1.f;
        aB = (int64_t)r * 131072;
        bB = (int64_t)bt * M20 + (int64_t)bx * 262144;
        cB = (int64_t)bt * M20 + (int64_t)r * 131072 + bx * 256;
    }
    gemm_body<128, 256, 2, 4, 1024, 1, false>(Ah, Al, aB, 1024, Bh, Bl, bB, 1024,
                                              nullptr, Ch, Cl, cB, 1024, scale, smem);
}

// ---------------------------------------------------------------- generic strided GEMM kernel
// Per-z offsets: (z>>4)*S1 + (z&15)*S2 elements.
template<int BM, int BN, int WGM, int WGN, int KDIM, int OUTMODE, bool A_SINGLE>
__global__ __launch_bounds__(WGM * WGN * 32)
void hmma_gemm(const h16* __restrict__ Ahi, const h16* __restrict__ Alo,
               int64_t aS1, int64_t aS2, int64_t lda,
               const h16* __restrict__ Bhi, const h16* __restrict__ Blo,
               int64_t bS1, int64_t bS2, int64_t ldb,
               float* __restrict__ Cf, h16* __restrict__ Chi, h16* __restrict__ Clo,
               int64_t cS1, int64_t cS2, int64_t ldc, float scale)
{
    extern __shared__ char smem[];
    const int z = blockIdx.z;
    const int64_t aB = (int64_t)(z >> 4) * aS1 + (int64_t)(z & 15) * aS2
                     + (int64_t)blockIdx.y * BM * lda;
    const int64_t bB = (int64_t)(z >> 4) * bS1 + (int64_t)(z & 15) * bS2
                     + (int64_t)blockIdx.x * BN * ldb;
    const int64_t cB = (int64_t)(z >> 4) * cS1 + (int64_t)(z & 15) * cS2
                     + (int64_t)blockIdx.y * BM * ldc + (int64_t)blockIdx.x * BN;
    gemm_body<BM, BN, WGM, WGN, KDIM, OUTMODE, A_SINGLE>(
        Ahi, Alo, aB, lda, Bhi, Blo, bB, ldb, Cf, Chi, Clo, cB, ldc, scale, smem);
}

// ---------------------------------------------------------------- softmax + talking heads + LN
// One block per (b,i): 16 heads x 1024 j. Reads g_wl fp16, writes g_wh fp16.
__global__ __launch_bounds__(256) void softtalk_kernel(
    const float* __restrict__ Wt, const float* __restrict__ gamma, const float* __restrict__ beta)
{
    extern __shared__ float sm[];        // [0:256) Wt, [256:272) gamma, [288:304) beta, rows @512
    float* rows = sm + 512;              // 16 rows x 1028
    const int tid = threadIdx.x;
    sm[tid] = Wt[tid];
    if (tid < 16) { sm[256 + tid] = gamma[tid]; sm[288 + tid] = beta[tid]; }
    const int b = blockIdx.x >> 10, i = blockIdx.x & 1023;
    const size_t base = ((size_t)b * 16) << 20;
    const size_t irow = (size_t)i * 1024;
#pragma unroll
    for (int h = 0; h < 16; ++h) {
        const uint2 pk = *(const uint2*)(g_wl + base + ((size_t)h << 20) + irow + tid * 4);
        const __half2 p0 = *(const __half2*)&pk.x;
        const __half2 p1 = *(const __half2*)&pk.y;
        float* r = rows + h * 1028 + tid * 4;
        r[0] = __low2float(p0); r[1] = __high2float(p0);
        r[2] = __low2float(p1); r[3] = __high2float(p1);
    }
    __syncthreads();

    const int wid = tid >> 5, lane = tid & 31;
#pragma unroll
    for (int rr = wid; rr < 16; rr += 8) {
        float* r = rows + rr * 1028;
        float mx = -1e30f;
        for (int j = lane; j < 1024; j += 32) mx = fmaxf(mx, r[j]);
#pragma unroll
        for (int o = 16; o; o >>= 1) mx = fmaxf(mx, __shfl_xor_sync(~0u, mx, o));
        float s = 0.f;
        for (int j = lane; j < 1024; j += 32) { float e = __expf(r[j] - mx); r[j] = e; s += e; }
#pragma unroll
        for (int o = 16; o; o >>= 1) s += __shfl_xor_sync(~0u, s, o);
        const float inv = 1.f / s;
        for (int j = lane; j < 1024; j += 32) r[j] *= inv;
    }
    __syncthreads();

#pragma unroll
    for (int jj = 0; jj < 4; ++jj) {
        const int j = tid + jj * 256;
        float o[16];
#pragma unroll
        for (int g = 0; g < 16; ++g) o[g] = 0.f;
#pragma unroll
        for (int h = 0; h < 16; ++h) {
            const float v = rows[h * 1028 + j];
#pragma unroll
            for (int g = 0; g < 16; ++g) o[g] = fmaf(v, sm[h * 16 + g], o[g]);
        }
        float mu = 0.f;
#pragma unroll
        for (int g = 0; g < 16; ++g) mu += o[g];
        mu *= 0.0625f;
        float var = 0.f;
#pragma unroll
        for (int g = 0; g < 16; ++g) { const float dd = o[g] - mu; var = fmaf(dd, dd, var); }
        var *= 0.0625f;
        const float rstd = rsqrtf(var + 1e-5f);
#pragma unroll
        for (int g = 0; g < 16; ++g) {
            const float val = (o[g] - mu) * rstd * sm[256 + g] + sm[288 + g];
            g_wh[base + ((size_t)g << 20) + irow + j] = __float2half_rn(val);
        }
    }
}

// ---------------------------------------------------------------- launch
extern "C" void kernel_launch(void* const* d_in, const int* in_sizes, int n_in,
                              void* d_out, int out_size) {
    (void)in_sizes; (void)n_in; (void)out_size;
    const float* x   = (const float*)d_in[0];
    const float* ctx = (const float*)d_in[1];
    const float* Wq  = (const float*)d_in[2];
    const float* Wkv = (const float*)d_in[3];
    const float* Wt  = (const float*)d_in[4];
    const float* gm  = (const float*)d_in[5];
    const float* bt  = (const float*)d_in[6];
    float* out = (float*)d_out;

    h16 *xhi, *xlo, *chi, *clo, *wqh, *wql, *wkh, *wkl;
    h16 *qh, *ql, *kh, *kl, *vth, *vtl, *wl, *wh;
    cudaGetSymbolAddress((void**)&xhi, g_xhi);   cudaGetSymbolAddress((void**)&xlo, g_xlo);
    cudaGetSymbolAddress((void**)&chi, g_chi);   cudaGetSymbolAddress((void**)&clo, g_clo);
    cudaGetSymbolAddress((void**)&wqh, g_wqhi);  cudaGetSymbolAddress((void**)&wql, g_wqlo);
    cudaGetSymbolAddress((void**)&wkh, g_wkhi);  cudaGetSymbolAddress((void**)&wkl, g_wklo);
    cudaGetSymbolAddress((void**)&qh,  g_qhi);   cudaGetSymbolAddress((void**)&ql,  g_qlo);
    cudaGetSymbolAddress((void**)&kh,  g_khi);   cudaGetSymbolAddress((void**)&kl,  g_klo);
    cudaGetSymbolAddress((void**)&vth, g_vthi);  cudaGetSymbolAddress((void**)&vtl, g_vtlo);
    cudaGetSymbolAddress((void**)&wl,  g_wl);    cudaGetSymbolAddress((void**)&wh,  g_wh);

    constexpr int SMEM_PROJ = 2 * (2 * 16384 + 2 * 32768);   // 196608
    constexpr int SMEM_DOT  = (2 * 16384 + 2 * 16384);       // 65536
    constexpr int SMEM_ATT  = 2 * (1 * 32768 + 2 * 8192);    // 98304
    constexpr int SST       = (512 + 16 * 1028) * 4;
    cudaFuncSetAttribute(proj3_kernel, cudaFuncAttributeMaxDynamicSharedMemorySize, SMEM_PROJ);
    cudaFuncSetAttribute(hmma_gemm<128, 128, 2, 4,   64, 2, false>,
                         cudaFuncAttributeMaxDynamicSharedMemorySize, SMEM_DOT);
    cudaFuncSetAttribute(hmma_gemm<256,  64, 4, 2, 1024, 0, true>,
                         cudaFuncAttributeMaxDynamicSharedMemorySize, SMEM_ATT);
    cudaFuncSetAttribute(softtalk_kernel, cudaFuncAttributeMaxDynamicSharedMemorySize, SST);

    const int64_t M20 = 1 << 20;

    split_kernel<<<4096, 256>>>(x, xhi, xlo);
    split_kernel<<<4096, 256>>>(ctx, chi, clo);
    tsplit_kernel<<<dim3(32, 32), dim3(32, 8)>>>(Wq,  wqh, wql, 1024, 1024);
    tsplit_kernel<<<dim3(64, 32), dim3(32, 8)>>>(Wkv, wkh, wkl, 1024, 2048);

    // merged q/k/vt projections: 384 CTAs (CTA tile 128x256)
    proj3_kernel<<<dim3(4, 96), 256, SMEM_PROJ>>>(
        xhi, xlo, chi, clo, wqh, wql, wkh, wkl, qh, ql, kh, kl, vth, vtl);

    // dots: per (b,h) 1024 x 1024 x 64 -> g_wl fp16 logits
    hmma_gemm<128, 128, 2, 4, 64, 2, false><<<dim3(8, 8, 64), 256, SMEM_DOT>>>(
        qh, ql, M20, 64, 1024,  kh, kl, M20, 64, 1024,
        nullptr, wl, nullptr, 16 * M20, M20, 1024, 1.f);
    // softmax + talking + LN: g_wl -> g_wh (both fp16)
    softtalk_kernel<<<4096, 256, SST>>>(Wt, gm, bt);
    // out = w @ v : per (b,h) 1024 x 64 x 1024 (CTA 256x64), A single-plane fp16 w
    hmma_gemm<256, 64, 4, 2, 1024, 0, true><<<dim3(1, 4, 64), 256, SMEM_ATT>>>(
        wh, nullptr, 16 * M20, M20, 1024,  vth, vtl, M20, 65536, 1024,
        out, nullptr, nullptr, M20, 64, 1024, 1.f);
}